// round 2
// baseline (speedup 1.0000x reference)
#include <cuda_runtime.h>

#define NN 10000
#define EE 160000
#define BB 8
#define TT 12
#define HH 64
#define TS 3
#define T0 9
#define ROWS (TS*NN*BB)   /* 240000 rows of 64 features */

/* ---------------- device scratch (no allocs allowed) ---------------- */
__device__ float  g_deg[NN];
__device__ float  g_dinv[NN];
__device__ float  g_self[NN];
__device__ int    g_cnt[NN];        /* histogram, then CSR cursor */
__device__ int    g_off[NN + 1];
__device__ int    g_csr_src[EE];
__device__ float  g_csr_w[EE];
__device__ float2 g_A[ROWS];            /* agg(x_t), width 2          */
__device__ float4 g_h1[TS * NN * 128];  /* relu(A@W1+b1)   61.4 MB    */
__device__ float4 g_C [TS * NN * 128];  /* agg(h1)         61.4 MB    */
__device__ float4 g_h2[TS * NN * 128];  /* relu(C@W2+b2)   61.4 MB    */

/* ---------------- small helpers ---------------- */
__device__ __forceinline__ void fma4(float4& a, float s, const float4 v) {
    a.x = fmaf(s, v.x, a.x); a.y = fmaf(s, v.y, a.y);
    a.z = fmaf(s, v.z, a.z); a.w = fmaf(s, v.w, a.w);
}
__device__ __forceinline__ float4 scale4(float s, const float4 v) {
    return make_float4(s * v.x, s * v.y, s * v.z, s * v.w);
}
__device__ __forceinline__ float4 relu4(float4 v) {
    v.x = fmaxf(v.x, 0.f); v.y = fmaxf(v.y, 0.f);
    v.z = fmaxf(v.z, 0.f); v.w = fmaxf(v.w, 0.f);
    return v;
}

/* ---------------- graph preprocessing ---------------- */
__global__ void k_zero() {
    int i = blockIdx.x * blockDim.x + threadIdx.x;
    if (i < NN) { g_deg[i] = 0.f; g_cnt[i] = 0; }
}

__global__ void k_deg(const int* __restrict__ ei, const float* __restrict__ w) {
    int e = blockIdx.x * blockDim.x + threadIdx.x;
    if (e >= EE) return;
    int d = ei[EE + e];
    atomicAdd(&g_deg[d], w[e]);
    atomicAdd(&g_cnt[d], 1);
}

__global__ void k_dinv() {
    int i = blockIdx.x * blockDim.x + threadIdx.x;
    if (i >= NN) return;
    /* self-loop weight 1 guarantees deg > 0 */
    float dv = rsqrtf(g_deg[i] + 1.0f);
    g_dinv[i] = dv;
    g_self[i] = dv * dv;
}

__global__ void k_scan() {   /* single block, 1024 threads: exclusive scan of g_cnt */
    __shared__ int ps[1024];
    int tid = threadIdx.x;
    int local[10];
    int s = 0;
    int base = tid * 10;
#pragma unroll
    for (int j = 0; j < 10; j++) {
        int gi = base + j;
        int v = (gi < NN) ? g_cnt[gi] : 0;
        local[j] = v; s += v;
    }
    ps[tid] = s; __syncthreads();
    for (int st = 1; st < 1024; st <<= 1) {
        int v = 0;
        if (tid >= st) v = ps[tid - st];
        __syncthreads();
        if (tid >= st) ps[tid] += v;
        __syncthreads();
    }
    int excl = (tid > 0) ? ps[tid - 1] : 0;
#pragma unroll
    for (int j = 0; j < 10; j++) {
        int gi = base + j;
        if (gi < NN) { g_off[gi] = excl; g_cnt[gi] = excl; /* cursor init */ }
        excl += local[j];
    }
    if (tid == 0) g_off[NN] = ps[1023];
}

__global__ void k_fill(const int* __restrict__ ei, const float* __restrict__ w) {
    int e = blockIdx.x * blockDim.x + threadIdx.x;
    if (e >= EE) return;
    int s = ei[e], d = ei[EE + e];
    float nr = g_dinv[s] * w[e] * g_dinv[d];
    int p = atomicAdd(&g_cnt[d], 1);
    g_csr_src[p] = s;
    g_csr_w[p] = nr;
}

/* ---------------- stage A: 2-wide aggregation of raw X (t = 9,10,11) ------- */
__global__ void k_aggA(const float* __restrict__ X) {
    int idx = blockIdx.x * blockDim.x + threadIdx.x;
    if (idx >= ROWS) return;
    int b = idx & 7;
    int nt = idx >> 3;
    int n = nt % NN;
    int t = nt / NN;
    const float2* base = (const float2*)X + (size_t)(b * TT + T0 + t) * NN;
    float2 x = base[n];
    float sf = g_self[n];
    float ax = sf * x.x, ay = sf * x.y;
    int j0 = g_off[n], j1 = g_off[n + 1];
    for (int j = j0; j < j1; j++) {
        int s = g_csr_src[j];
        float nr = g_csr_w[j];
        float2 xs = base[s];
        ax = fmaf(nr, xs.x, ax);
        ay = fmaf(nr, xs.y, ay);
    }
    g_A[idx] = make_float2(ax, ay);
}

/* ---------------- h1 = relu(A @ W1 + b1), elementwise over float4 --------- */
__global__ void k_h1(const float* __restrict__ W1, const float* __restrict__ b1) {
    int i = blockIdx.x * blockDim.x + threadIdx.x;
    if (i >= ROWS * 16) return;
    int row = i >> 4, q = i & 15;
    float2 a = g_A[row];
    float4 w0 = __ldg((const float4*)W1 + q);        /* W1[0][4q..] */
    float4 w1 = __ldg((const float4*)W1 + 16 + q);   /* W1[1][4q..] */
    float4 bb = __ldg((const float4*)b1 + q);
    float4 v;
    v.x = fmaxf(fmaf(a.x, w0.x, fmaf(a.y, w1.x, bb.x)), 0.f);
    v.y = fmaxf(fmaf(a.x, w0.y, fmaf(a.y, w1.y, bb.y)), 0.f);
    v.z = fmaxf(fmaf(a.x, w0.z, fmaf(a.y, w1.z, bb.z)), 0.f);
    v.w = fmaxf(fmaf(a.x, w0.w, fmaf(a.y, w1.w, bb.w)), 0.f);
    g_h1[i] = v;
}

/* ---------------- stage C: 64-wide gather aggregation, warp per node ------ */
__global__ void k_aggC(int t) {
    int g = blockIdx.x * blockDim.x + threadIdx.x;
    int wi = g >> 5;
    if (wi >= NN) return;
    int lane = g & 31;
    const float4* h1t = g_h1 + (size_t)t * NN * 128;
    const float4* rn = h1t + (size_t)wi * 128 + lane;
    float sf = g_self[wi];
    float4 a0 = scale4(sf, rn[0]);
    float4 a1 = scale4(sf, rn[32]);
    float4 a2 = scale4(sf, rn[64]);
    float4 a3 = scale4(sf, rn[96]);
    int j0 = g_off[wi], j1 = g_off[wi + 1];
    for (int j = j0; j < j1; j++) {
        int s = g_csr_src[j];
        float nr = g_csr_w[j];
        const float4* rs = h1t + (size_t)s * 128 + lane;
        fma4(a0, nr, rs[0]);
        fma4(a1, nr, rs[32]);
        fma4(a2, nr, rs[64]);
        fma4(a3, nr, rs[96]);
    }
    float4* dst = g_C + (size_t)t * NN * 128 + (size_t)wi * 128 + lane;
    dst[0] = a0; dst[32] = a1; dst[64] = a2; dst[96] = a3;
}

/* ---------------- F1: h2 = relu(C @ W2 + b2), thread per row -------------- */
__global__ __launch_bounds__(256) void k_f1(const float* __restrict__ W2,
                                            const float* __restrict__ b2) {
    __shared__ float4 W2s[1024];  /* [ci][hq] */
    __shared__ float4 b2s[16];
    int tid = threadIdx.x;
    for (int i = tid; i < 1024; i += 256) W2s[i] = ((const float4*)W2)[i];
    if (tid < 16) b2s[tid] = ((const float4*)b2)[tid];
    __syncthreads();
    int row = blockIdx.x * 256 + tid;
    if (row >= ROWS) return;
    const float4* src = g_C + (size_t)row * 16;
    float4 acc[16];
#pragma unroll
    for (int q = 0; q < 16; q++) acc[q] = b2s[q];
    for (int cq = 0; cq < 16; cq++) {
        float4 x = src[cq];
        const float4* w = W2s + cq * 64;
#pragma unroll
        for (int q = 0; q < 16; q++) {
            float4 w0 = w[q], w1 = w[16 + q], w2 = w[32 + q], w3 = w[48 + q];
            acc[q].x += x.x * w0.x + x.y * w1.x + x.z * w2.x + x.w * w3.x;
            acc[q].y += x.x * w0.y + x.y * w1.y + x.z * w2.y + x.w * w3.y;
            acc[q].z += x.x * w0.z + x.y * w1.z + x.z * w2.z + x.w * w3.z;
            acc[q].w += x.x * w0.w + x.y * w1.w + x.z * w2.w + x.w * w3.w;
        }
    }
    float4* dst = g_h2 + (size_t)row * 16;
#pragma unroll
    for (int q = 0; q < 16; q++) dst[q] = relu4(acc[q]);
}

/* ---------------- F2: temporal convs (only needed taps) + head ------------ */
#define F2_SMEM ((5 * 4096 + 192) * 4)
__global__ __launch_bounds__(256) void k_f2(const float* __restrict__ tc1w,
                                            const float* __restrict__ tc1b,
                                            const float* __restrict__ tc2w,
                                            const float* __restrict__ tc2b,
                                            const float* __restrict__ ow,
                                            const float* __restrict__ ob,
                                            float* __restrict__ out) {
    extern __shared__ float sm[];
    float* w10 = sm;            /* [ci][co] = tc1_w[co][ci][0] */
    float* w11 = sm + 4096;
    float* w12 = sm + 8192;
    float* w20 = sm + 12288;    /* [co2][ci] = tc2_w[co2][ci][0] */
    float* w21 = sm + 16384;
    float* tb1 = sm + 20480;
    float* tb2 = tb1 + 64;
    float* ows = tb2 + 64;
    int tid = threadIdx.x;
    for (int i = tid; i < 4096; i += 256) {
        int ci = i >> 6, co = i & 63;
        int s1 = (co * 64 + ci) * 3;
        w10[i] = tc1w[s1];
        w11[i] = tc1w[s1 + 1];
        w12[i] = tc1w[s1 + 2];
        w20[i] = tc2w[i * 3];
        w21[i] = tc2w[i * 3 + 1];
    }
    if (tid < 64) { tb1[tid] = tc1b[tid]; tb2[tid] = tc2b[tid]; ows[tid] = ow[tid]; }
    __syncthreads();
    int idx = blockIdx.x * 256 + tid;
    if (idx >= BB * NN) return;
    int n = idx % NN, b = idx / NN;
    const float* h2f = (const float*)g_h2;
    const float* r9  = h2f + ((size_t)(0 * NN + n) * 8 + b) * 64;
    const float* r10 = h2f + ((size_t)(1 * NN + n) * 8 + b) * 64;
    const float* r11 = h2f + ((size_t)(2 * NN + n) * 8 + b) * 64;

    float4 a10[16], a11[16];
    const float4* tb1q = (const float4*)tb1;
#pragma unroll
    for (int q = 0; q < 16; q++) { a10[q] = tb1q[q]; a11[q] = tb1q[q]; }

    const float4* p0b = (const float4*)w10;
    const float4* p1b = (const float4*)w11;
    const float4* p2b = (const float4*)w12;
    for (int ci = 0; ci < 64; ci++) {
        float s9 = r9[ci], s10 = r10[ci], s11 = r11[ci];
        const float4* p0 = p0b + ci * 16;
        const float4* p1 = p1b + ci * 16;
        const float4* p2 = p2b + ci * 16;
#pragma unroll
        for (int q = 0; q < 16; q++) {
            float4 w0 = p0[q], w1 = p1[q], w2 = p2[q];
            a10[q].x += s9 * w0.x + s10 * w1.x + s11 * w2.x;
            a10[q].y += s9 * w0.y + s10 * w1.y + s11 * w2.y;
            a10[q].z += s9 * w0.z + s10 * w1.z + s11 * w2.z;
            a10[q].w += s9 * w0.w + s10 * w1.w + s11 * w2.w;
            a11[q].x += s10 * w0.x + s11 * w1.x;
            a11[q].y += s10 * w0.y + s11 * w1.y;
            a11[q].z += s10 * w0.z + s11 * w1.z;
            a11[q].w += s10 * w0.w + s11 * w1.w;
        }
    }
#pragma unroll
    for (int q = 0; q < 16; q++) { a10[q] = relu4(a10[q]); a11[q] = relu4(a11[q]); }

    float acc = 0.f;
    const float4* pab = (const float4*)w20;
    const float4* pbb = (const float4*)w21;
    for (int co = 0; co < 64; co++) {
        float s = tb2[co];
        const float4* pa = pab + co * 16;
        const float4* pb = pbb + co * 16;
#pragma unroll
        for (int q = 0; q < 16; q++) {
            float4 wa = pa[q], wb = pb[q];
            s += a10[q].x * wa.x + a10[q].y * wa.y + a10[q].z * wa.z + a10[q].w * wa.w
               + a11[q].x * wb.x + a11[q].y * wb.y + a11[q].z * wb.z + a11[q].w * wb.w;
        }
        acc += fmaxf(s, 0.f) * ows[co];
    }
    out[idx] = acc + ob[0];
}

/* ---------------- launch ---------------- */
extern "C" void kernel_launch(void* const* d_in, const int* in_sizes, int n_in,
                              void* d_out, int out_size) {
    const float* X    = (const float*)d_in[0];
    const int*   ei   = (const int*)d_in[1];
    const float* ew   = (const float*)d_in[2];
    const float* W1   = (const float*)d_in[3];
    const float* b1   = (const float*)d_in[4];
    const float* W2   = (const float*)d_in[5];
    const float* b2   = (const float*)d_in[6];
    const float* tc1w = (const float*)d_in[7];
    const float* tc1b = (const float*)d_in[8];
    const float* tc2w = (const float*)d_in[9];
    const float* tc2b = (const float*)d_in[10];
    const float* ow   = (const float*)d_in[11];
    const float* ob   = (const float*)d_in[12];
    float* out = (float*)d_out;

    cudaFuncSetAttribute(k_f2, cudaFuncAttributeMaxDynamicSharedMemorySize, F2_SMEM);

    k_zero<<<(NN + 255) / 256, 256>>>();
    k_deg<<<(EE + 255) / 256, 256>>>(ei, ew);
    k_dinv<<<(NN + 255) / 256, 256>>>();
    k_scan<<<1, 1024>>>();
    k_fill<<<(EE + 255) / 256, 256>>>(ei, ew);
    k_aggA<<<(ROWS + 255) / 256, 256>>>(X);
    k_h1<<<(ROWS * 16 + 255) / 256, 256>>>(W1, b1);
    for (int t = 0; t < TS; t++)
        k_aggC<<<(NN * 32 + 255) / 256, 256>>>(t);
    k_f1<<<(ROWS + 255) / 256, 256>>>(W2, b2);
    k_f2<<<(BB * NN + 255) / 256, 256, F2_SMEM>>>(tc1w, tc1b, tc2w, tc2b, ow, ob, out);
}

// round 3
// speedup vs baseline: 1.2080x; 1.2080x over previous
#include <cuda_runtime.h>

#define NN 10000
#define EE 160000
#define BB 8
#define TT 12
#define HH 64
#define TS 3
#define T0 9
#define ROWS (TS*NN*BB)   /* 240000 rows of 64 features */

typedef unsigned long long ull;

/* ---------------- device scratch (no allocs allowed) ---------------- */
__device__ float  g_deg[NN];
__device__ float  g_dinv[NN];
__device__ float  g_self[NN];
__device__ int    g_cnt[NN];        /* histogram, then CSR cursor */
__device__ int    g_off[NN + 1];
__device__ int    g_csr_src[EE];
__device__ float  g_csr_w[EE];
__device__ float2 g_A[ROWS];            /* agg(x_t), width 2          */
__device__ float4 g_h1[TS * NN * 128];  /* relu(A@W1+b1) [t][n][b][64] */
__device__ float4 g_C [TS * NN * 128];  /* agg(h1)       [t][n][b][64] */
__device__ float  g_h2[TS * 64 * BB * NN]; /* relu(C@W2+b2) TRANSPOSED [t][ci][b][n] */

/* ---------------- packed f32x2 helpers ---------------- */
__device__ __forceinline__ ull fma2(ull a, ull b, ull c) {
    ull d;
    asm("fma.rn.f32x2 %0, %1, %2, %3;" : "=l"(d) : "l"(a), "l"(b), "l"(c));
    return d;
}
__device__ __forceinline__ ull bc2(float s) {
    ull r;
    asm("mov.b64 %0, {%1, %1};" : "=l"(r) : "r"(__float_as_uint(s)));
    return r;
}
__device__ __forceinline__ float2 unp(ull v) {
    unsigned lo, hi;
    asm("mov.b64 {%0, %1}, %2;" : "=r"(lo), "=r"(hi) : "l"(v));
    return make_float2(__uint_as_float(lo), __uint_as_float(hi));
}
__device__ __forceinline__ ull pk2(float a, float b) {
    ull r;
    asm("mov.b64 %0, {%1, %2};" : "=l"(r) : "r"(__float_as_uint(a)), "r"(__float_as_uint(b)));
    return r;
}

__device__ __forceinline__ void fma4(float4& a, float s, const float4 v) {
    a.x = fmaf(s, v.x, a.x); a.y = fmaf(s, v.y, a.y);
    a.z = fmaf(s, v.z, a.z); a.w = fmaf(s, v.w, a.w);
}
__device__ __forceinline__ float4 scale4(float s, const float4 v) {
    return make_float4(s * v.x, s * v.y, s * v.z, s * v.w);
}

/* ---------------- graph preprocessing ---------------- */
__global__ void k_zero() {
    int i = blockIdx.x * blockDim.x + threadIdx.x;
    if (i < NN) { g_deg[i] = 0.f; g_cnt[i] = 0; }
}

__global__ void k_deg(const int* __restrict__ ei, const float* __restrict__ w) {
    int e = blockIdx.x * blockDim.x + threadIdx.x;
    if (e >= EE) return;
    int d = ei[EE + e];
    atomicAdd(&g_deg[d], w[e]);
    atomicAdd(&g_cnt[d], 1);
}

__global__ void k_dinv() {
    int i = blockIdx.x * blockDim.x + threadIdx.x;
    if (i >= NN) return;
    float dv = rsqrtf(g_deg[i] + 1.0f);   /* self-loop weight 1 => deg>0 */
    g_dinv[i] = dv;
    g_self[i] = dv * dv;
}

/* shuffle-based single-block scan: 3 barriers instead of 20 */
__global__ void k_scan() {
    __shared__ int wsum[32];
    int tid = threadIdx.x, lane = tid & 31, w = tid >> 5;
    int local[10];
    int s = 0;
    int base = tid * 10;
#pragma unroll
    for (int j = 0; j < 10; j++) {
        int gi = base + j;
        int v = (gi < NN) ? g_cnt[gi] : 0;
        local[j] = v; s += v;
    }
    int tot = s;
#pragma unroll
    for (int d = 1; d < 32; d <<= 1) {
        int v = __shfl_up_sync(0xffffffffu, s, d);
        if (lane >= d) s += v;
    }
    if (lane == 31) wsum[w] = s;
    __syncthreads();
    if (w == 0) {
        int v = wsum[lane];
#pragma unroll
        for (int d = 1; d < 32; d <<= 1) {
            int u = __shfl_up_sync(0xffffffffu, v, d);
            if (lane >= d) v += u;
        }
        wsum[lane] = v;
    }
    __syncthreads();
    int excl = s - tot + (w ? wsum[w - 1] : 0);
#pragma unroll
    for (int j = 0; j < 10; j++) {
        int gi = base + j;
        if (gi < NN) { g_off[gi] = excl; g_cnt[gi] = excl; }
        excl += local[j];
    }
    if (tid == 1023) g_off[NN] = excl;
}

__global__ void k_fill(const int* __restrict__ ei, const float* __restrict__ w) {
    int e = blockIdx.x * blockDim.x + threadIdx.x;
    if (e >= EE) return;
    int s = ei[e], d = ei[EE + e];
    float nr = g_dinv[s] * w[e] * g_dinv[d];
    int p = atomicAdd(&g_cnt[d], 1);
    g_csr_src[p] = s;
    g_csr_w[p] = nr;
}

/* ---------------- stage A: 2-wide aggregation of raw X (t = 9,10,11) ------- */
__global__ void k_aggA(const float* __restrict__ X) {
    int idx = blockIdx.x * blockDim.x + threadIdx.x;
    if (idx >= ROWS) return;
    int b = idx & 7;
    int nt = idx >> 3;
    int n = nt % NN;
    int t = nt / NN;
    const float2* base = (const float2*)X + (size_t)(b * TT + T0 + t) * NN;
    float2 x = base[n];
    float sf = g_self[n];
    float ax = sf * x.x, ay = sf * x.y;
    int j0 = g_off[n], j1 = g_off[n + 1];
    for (int j = j0; j < j1; j++) {
        int s = g_csr_src[j];
        float nr = g_csr_w[j];
        float2 xs = base[s];
        ax = fmaf(nr, xs.x, ax);
        ay = fmaf(nr, xs.y, ay);
    }
    g_A[idx] = make_float2(ax, ay);
}

/* ---------------- h1 = relu(A @ W1 + b1) ---------------- */
__global__ void k_h1(const float* __restrict__ W1, const float* __restrict__ b1) {
    int i = blockIdx.x * blockDim.x + threadIdx.x;
    if (i >= ROWS * 16) return;
    int row = i >> 4, q = i & 15;
    float2 a = g_A[row];
    float4 w0 = __ldg((const float4*)W1 + q);
    float4 w1 = __ldg((const float4*)W1 + 16 + q);
    float4 bb = __ldg((const float4*)b1 + q);
    float4 v;
    v.x = fmaxf(fmaf(a.x, w0.x, fmaf(a.y, w1.x, bb.x)), 0.f);
    v.y = fmaxf(fmaf(a.x, w0.y, fmaf(a.y, w1.y, bb.y)), 0.f);
    v.z = fmaxf(fmaf(a.x, w0.z, fmaf(a.y, w1.z, bb.z)), 0.f);
    v.w = fmaxf(fmaf(a.x, w0.w, fmaf(a.y, w1.w, bb.w)), 0.f);
    g_h1[i] = v;
}

/* ---------------- stage C: 64-wide gather aggregation, warp per node ------ */
__global__ void k_aggC() {
    int t = blockIdx.y;
    int g = blockIdx.x * blockDim.x + threadIdx.x;
    int wi = g >> 5;
    if (wi >= NN) return;
    int lane = g & 31;
    const float4* h1t = g_h1 + (size_t)t * NN * 128;
    const float4* rn = h1t + (size_t)wi * 128 + lane;
    float sf = g_self[wi];
    float4 a0 = scale4(sf, rn[0]);
    float4 a1 = scale4(sf, rn[32]);
    float4 a2 = scale4(sf, rn[64]);
    float4 a3 = scale4(sf, rn[96]);
    int j0 = g_off[wi], j1 = g_off[wi + 1];
    for (int j = j0; j < j1; j++) {
        int s = g_csr_src[j];
        float nr = g_csr_w[j];
        const float4* rs = h1t + (size_t)s * 128 + lane;
        fma4(a0, nr, rs[0]);
        fma4(a1, nr, rs[32]);
        fma4(a2, nr, rs[64]);
        fma4(a3, nr, rs[96]);
    }
    float4* dst = g_C + (size_t)t * NN * 128 + (size_t)wi * 128 + lane;
    dst[0] = a0; dst[32] = a1; dst[64] = a2; dst[96] = a3;
}

/* ---------------- F1: h2T = relu(C @ W2 + b2), packed FFMA2 --------------- */
__global__ __launch_bounds__(256) void k_f1(const float* __restrict__ W2,
                                            const float* __restrict__ b2) {
    __shared__ __align__(16) ull W2s[2048];  /* [ci][32 pairs] */
    __shared__ __align__(16) ull b2s[32];
    int tid = threadIdx.x;
    for (int i = tid; i < 1024; i += 256)
        ((ulonglong2*)W2s)[i] = ((const ulonglong2*)W2)[i];
    if (tid < 16) ((ulonglong2*)b2s)[tid] = ((const ulonglong2*)b2)[tid];
    __syncthreads();
    int row = blockIdx.x * 256 + tid;
    if (row >= ROWS) return;
    const float4* src = g_C + (size_t)row * 16;
    ull acc[32];
#pragma unroll
    for (int p = 0; p < 32; p++) acc[p] = b2s[p];
#pragma unroll 4
    for (int cq = 0; cq < 16; cq++) {
        float4 x = src[cq];
        ull x0 = bc2(x.x), x1 = bc2(x.y), x2 = bc2(x.z), x3 = bc2(x.w);
        const ulonglong2* w0 = (const ulonglong2*)(W2s + (4 * cq + 0) * 32);
        const ulonglong2* w1 = (const ulonglong2*)(W2s + (4 * cq + 1) * 32);
        const ulonglong2* w2 = (const ulonglong2*)(W2s + (4 * cq + 2) * 32);
        const ulonglong2* w3 = (const ulonglong2*)(W2s + (4 * cq + 3) * 32);
#pragma unroll
        for (int p2 = 0; p2 < 16; p2++) {
            ulonglong2 a = w0[p2], bw = w1[p2], c = w2[p2], d = w3[p2];
            acc[2 * p2]     = fma2(x0, a.x,  acc[2 * p2]);
            acc[2 * p2]     = fma2(x1, bw.x, acc[2 * p2]);
            acc[2 * p2]     = fma2(x2, c.x,  acc[2 * p2]);
            acc[2 * p2]     = fma2(x3, d.x,  acc[2 * p2]);
            acc[2 * p2 + 1] = fma2(x0, a.y,  acc[2 * p2 + 1]);
            acc[2 * p2 + 1] = fma2(x1, bw.y, acc[2 * p2 + 1]);
            acc[2 * p2 + 1] = fma2(x2, c.y,  acc[2 * p2 + 1]);
            acc[2 * p2 + 1] = fma2(x3, d.y,  acc[2 * p2 + 1]);
        }
    }
    /* write transposed: h2T[((t*64+ci)*8+b)*NN + n] */
    int t = row / (NN * 8);
    int rr = row - t * (NN * 8);
    int n = rr >> 3, b = rr & 7;
    float* dst = g_h2 + (size_t)t * 64 * 8 * NN + (size_t)b * NN + n;
#pragma unroll
    for (int p = 0; p < 32; p++) {
        float2 v = unp(acc[p]);
        dst[(size_t)(2 * p) * 8 * NN]     = fmaxf(v.x, 0.f);
        dst[(size_t)(2 * p + 1) * 8 * NN] = fmaxf(v.y, 0.f);
    }
}

/* ---------------- F2: temporal convs (needed taps) + head, packed --------- */
#define F2_SMEM ((5 * 4096 + 192) * 4)
__global__ __launch_bounds__(128) void k_f2(const float* __restrict__ tc1w,
                                            const float* __restrict__ tc1b,
                                            const float* __restrict__ tc2w,
                                            const float* __restrict__ tc2b,
                                            const float* __restrict__ ow,
                                            const float* __restrict__ ob,
                                            float* __restrict__ out) {
    extern __shared__ __align__(16) float sm[];
    float* w10 = sm;            /* [ci][co] = tc1_w[co][ci][tap] */
    float* w11 = sm + 4096;
    float* w12 = sm + 8192;
    float* w20 = sm + 12288;    /* [co2][ci] = tc2_w[co2][ci][tap] */
    float* w21 = sm + 16384;
    float* tb1 = sm + 20480;
    float* tb2 = tb1 + 64;
    float* ows = tb2 + 64;
    int tid = threadIdx.x;
    for (int i = tid; i < 4096; i += 128) {
        int ci = i >> 6, co = i & 63;
        int s1 = (co * 64 + ci) * 3;
        w10[i] = tc1w[s1];
        w11[i] = tc1w[s1 + 1];
        w12[i] = tc1w[s1 + 2];
        w20[i] = tc2w[i * 3];
        w21[i] = tc2w[i * 3 + 1];
    }
    if (tid < 64) { tb1[tid] = tc1b[tid]; tb2[tid] = tc2b[tid]; ows[tid] = ow[tid]; }
    __syncthreads();
    int idx = blockIdx.x * 128 + tid;
    if (idx >= BB * NN) return;
    int n = idx % NN, b = idx / NN;

    ull a10[32], a11[32];
    const ull* tb1p = (const ull*)tb1;
#pragma unroll
    for (int p = 0; p < 32; p++) { a10[p] = tb1p[p]; a11[p] = tb1p[p]; }

    const float* hp = g_h2 + (size_t)b * NN + n;   /* + (t*64+ci)*8*NN */
    float s9  = hp[0];
    float s10 = hp[(size_t)64 * 8 * NN];
    float s11 = hp[(size_t)128 * 8 * NN];
    for (int ci = 0; ci < 64; ci++) {
        float n9 = 0.f, n10 = 0.f, n11 = 0.f;
        if (ci < 63) {   /* prefetch next row */
            n9  = hp[(size_t)(ci + 1) * 8 * NN];
            n10 = hp[(size_t)(64 + ci + 1) * 8 * NN];
            n11 = hp[(size_t)(128 + ci + 1) * 8 * NN];
        }
        ull b9 = bc2(s9), b10 = bc2(s10), b11 = bc2(s11);
        const ulonglong2* p0 = (const ulonglong2*)(w10 + ci * 64);
        const ulonglong2* p1 = (const ulonglong2*)(w11 + ci * 64);
        const ulonglong2* p2 = (const ulonglong2*)(w12 + ci * 64);
#pragma unroll
        for (int q = 0; q < 16; q++) {
            ulonglong2 t0 = p0[q], t1 = p1[q], t2 = p2[q];
            a10[2 * q]     = fma2(b9,  t0.x, a10[2 * q]);
            a10[2 * q]     = fma2(b10, t1.x, a10[2 * q]);
            a10[2 * q]     = fma2(b11, t2.x, a10[2 * q]);
            a10[2 * q + 1] = fma2(b9,  t0.y, a10[2 * q + 1]);
            a10[2 * q + 1] = fma2(b10, t1.y, a10[2 * q + 1]);
            a10[2 * q + 1] = fma2(b11, t2.y, a10[2 * q + 1]);
            a11[2 * q]     = fma2(b10, t0.x, a11[2 * q]);
            a11[2 * q]     = fma2(b11, t1.x, a11[2 * q]);
            a11[2 * q + 1] = fma2(b10, t0.y, a11[2 * q + 1]);
            a11[2 * q + 1] = fma2(b11, t1.y, a11[2 * q + 1]);
        }
        s9 = n9; s10 = n10; s11 = n11;
    }
#pragma unroll
    for (int p = 0; p < 32; p++) {
        float2 u = unp(a10[p]);
        a10[p] = pk2(fmaxf(u.x, 0.f), fmaxf(u.y, 0.f));
        float2 v = unp(a11[p]);
        a11[p] = pk2(fmaxf(v.x, 0.f), fmaxf(v.y, 0.f));
    }

    float acc = 0.f;
    for (int co = 0; co < 64; co++) {
        ull sp0 = 0, sp1 = 0, sp2 = 0, sp3 = 0;
        const ulonglong2* pa = (const ulonglong2*)(w20 + co * 64);
        const ulonglong2* pb = (const ulonglong2*)(w21 + co * 64);
#pragma unroll
        for (int q = 0; q < 16; q++) {
            ulonglong2 wa = pa[q], wb = pb[q];
            sp0 = fma2(a10[2 * q],     wa.x, sp0);
            sp1 = fma2(a10[2 * q + 1], wa.y, sp1);
            sp2 = fma2(a11[2 * q],     wb.x, sp2);
            sp3 = fma2(a11[2 * q + 1], wb.y, sp3);
        }
        float2 u0 = unp(sp0), u1 = unp(sp1), u2 = unp(sp2), u3 = unp(sp3);
        float s = tb2[co] + ((u0.x + u0.y) + (u1.x + u1.y))
                          + ((u2.x + u2.y) + (u3.x + u3.y));
        acc = fmaf(fmaxf(s, 0.f), ows[co], acc);
    }
    out[idx] = acc + ob[0];
}

/* ---------------- launch ---------------- */
extern "C" void kernel_launch(void* const* d_in, const int* in_sizes, int n_in,
                              void* d_out, int out_size) {
    const float* X    = (const float*)d_in[0];
    const int*   ei   = (const int*)d_in[1];
    const float* ew   = (const float*)d_in[2];
    const float* W1   = (const float*)d_in[3];
    const float* b1   = (const float*)d_in[4];
    const float* W2   = (const float*)d_in[5];
    const float* b2   = (const float*)d_in[6];
    const float* tc1w = (const float*)d_in[7];
    const float* tc1b = (const float*)d_in[8];
    const float* tc2w = (const float*)d_in[9];
    const float* tc2b = (const float*)d_in[10];
    const float* ow   = (const float*)d_in[11];
    const float* ob   = (const float*)d_in[12];
    float* out = (float*)d_out;

    cudaFuncSetAttribute(k_f2, cudaFuncAttributeMaxDynamicSharedMemorySize, F2_SMEM);

    k_zero<<<(NN + 255) / 256, 256>>>();
    k_deg<<<(EE + 255) / 256, 256>>>(ei, ew);
    k_dinv<<<(NN + 255) / 256, 256>>>();
    k_scan<<<1, 1024>>>();
    k_fill<<<(EE + 255) / 256, 256>>>(ei, ew);
    k_aggA<<<(ROWS + 255) / 256, 256>>>(X);
    k_h1<<<(ROWS * 16 + 255) / 256, 256>>>(W1, b1);
    dim3 gC((NN * 32 + 255) / 256, TS);
    k_aggC<<<gC, 256>>>();
    k_f1<<<(ROWS + 255) / 256, 256>>>(W2, b2);
    k_f2<<<(BB * NN + 127) / 128, 128, F2_SMEM>>>(tc1w, tc1b, tc2w, tc2b, ow, ob, out);
}

// round 4
// speedup vs baseline: 1.4108x; 1.1679x over previous
#include <cuda_runtime.h>

#define NN 10000
#define EE 160000
#define BB 8
#define TT 12
#define HH 64
#define TS 3
#define T0 9
#define ROWS (TS*NN*BB)   /* 240000 rows of 64 features */
#define NB  (BB*NN)       /* 80000 (n,b) pairs per (t,ci) plane in g_h2 */

typedef unsigned long long ull;

/* ---------------- device scratch (no allocs allowed) ---------------- */
__device__ float  g_deg[NN];
__device__ float  g_self[NN];
__device__ float  g_dinv[NN];
__device__ int    g_cnt[NN];        /* histogram, then CSR fill cursor */
__device__ int    g_off[NN];
__device__ int    g_end[NN];
__device__ int    g_alloc;
__device__ int    g_csr_src[EE];
__device__ float  g_csr_w[EE];
__device__ float4 g_h1[TS * NN * 128];  /* relu(agg(X)@W1+b1)  [t][n][b][64]  61.4MB */
__device__ float  g_h2[TS * 64 * NB];   /* relu(agg(h1)@W2+b2) [t][co][n*8+b] 61.4MB */

/* ---------------- packed f32x2 helpers ---------------- */
__device__ __forceinline__ ull fma2(ull a, ull b, ull c) {
    ull d;
    asm("fma.rn.f32x2 %0, %1, %2, %3;" : "=l"(d) : "l"(a), "l"(b), "l"(c));
    return d;
}
__device__ __forceinline__ ull bc2(float s) {
    ull r;
    asm("mov.b64 %0, {%1, %1};" : "=l"(r) : "r"(__float_as_uint(s)));
    return r;
}
__device__ __forceinline__ float2 unp(ull v) {
    unsigned lo, hi;
    asm("mov.b64 {%0, %1}, %2;" : "=r"(lo), "=r"(hi) : "l"(v));
    return make_float2(__uint_as_float(lo), __uint_as_float(hi));
}
__device__ __forceinline__ ull pk2(float a, float b) {
    ull r;
    asm("mov.b64 %0, {%1, %2};" : "=l"(r) : "r"(__float_as_uint(a)), "r"(__float_as_uint(b)));
    return r;
}
__device__ __forceinline__ void fma4(float4& a, float s, const float4 v) {
    a.x = fmaf(s, v.x, a.x); a.y = fmaf(s, v.y, a.y);
    a.z = fmaf(s, v.z, a.z); a.w = fmaf(s, v.w, a.w);
}
__device__ __forceinline__ float4 scale4(float s, const float4 v) {
    return make_float4(s * v.x, s * v.y, s * v.z, s * v.w);
}

/* ---------------- graph preprocessing ---------------- */
__global__ void k_zero() {
    int i = blockIdx.x * blockDim.x + threadIdx.x;
    if (i < NN) { g_deg[i] = 0.f; g_cnt[i] = 0; }
    if (i == 0) g_alloc = 0;
}

__global__ void k_deg(const int* __restrict__ ei, const float* __restrict__ w) {
    int e = blockIdx.x * blockDim.x + threadIdx.x;
    if (e >= EE) return;
    int d = ei[EE + e];
    atomicAdd(&g_deg[d], w[e]);
    atomicAdd(&g_cnt[d], 1);
}

/* dinv + CSR segment allocation (order-free: no prefix scan needed) */
__global__ void k_dinv() {
    int i = blockIdx.x * blockDim.x + threadIdx.x;
    int lane = threadIdx.x & 31;
    int valid = (i < NN);
    int c = valid ? g_cnt[i] : 0;
    int incl = c;
#pragma unroll
    for (int d = 1; d < 32; d <<= 1) {
        int v = __shfl_up_sync(0xffffffffu, incl, d);
        if (lane >= d) incl += v;
    }
    int wtot = __shfl_sync(0xffffffffu, incl, 31);
    int base = 0;
    if (lane == 31 && wtot > 0) base = atomicAdd(&g_alloc, wtot);
    base = __shfl_sync(0xffffffffu, base, 31);
    if (!valid) return;
    int off = base + incl - c;
    g_off[i] = off;
    g_end[i] = off + c;
    g_cnt[i] = off;                    /* fill cursor */
    float dv = rsqrtf(g_deg[i] + 1.0f);   /* self-loop weight 1 => deg>0 */
    g_dinv[i] = dv;
    g_self[i] = dv * dv;
}

__global__ void k_fill(const int* __restrict__ ei, const float* __restrict__ w) {
    int e = blockIdx.x * blockDim.x + threadIdx.x;
    if (e >= EE) return;
    int s = ei[e], d = ei[EE + e];
    float nr = g_dinv[s] * w[e] * g_dinv[d];
    int p = atomicAdd(&g_cnt[d], 1);
    g_csr_src[p] = s;
    g_csr_w[p] = nr;
}

/* ------- fused stage A: 2-wide agg of X + h1 = relu(A@W1+b1), staged ------ */
__global__ __launch_bounds__(128) void k_aggAH1(const float* __restrict__ X,
                                                const float* __restrict__ W1,
                                                const float* __restrict__ b1) {
    __shared__ __align__(16) float sS[128 * 68];   /* 128 rows, pad 68 (17 f4) */
    __shared__ __align__(16) float sW1[128];
    __shared__ __align__(16) float sb1[64];
    int tid = threadIdx.x;
    if (tid < 128) sW1[tid] = W1[tid];
    if (tid < 64)  sb1[tid] = b1[tid];
    __syncthreads();

    int blk0 = blockIdx.x * 128;
    int idx = blk0 + tid;
    int nrows = ROWS - blk0; if (nrows > 128) nrows = 128;

    if (tid < nrows) {
        int b = idx & 7;
        int nt = idx >> 3;
        int n = nt % NN;
        int t = nt / NN;
        const float2* base = (const float2*)X + (size_t)(b * TT + T0 + t) * NN;
        float2 x = base[n];
        float sf = g_self[n];
        float ax = sf * x.x, ay = sf * x.y;
        int j0 = g_off[n], j1 = g_end[n];
        for (int j = j0; j < j1; j++) {
            int s = g_csr_src[j];
            float nr = g_csr_w[j];
            float2 xs = base[s];
            ax = fmaf(nr, xs.x, ax);
            ay = fmaf(nr, xs.y, ay);
        }
        /* h1 row = relu(ax*W1[0] + ay*W1[1] + b1) */
        float4* row = (float4*)(sS + tid * 68);
        const float4* w0 = (const float4*)sW1;
        const float4* w1 = (const float4*)(sW1 + 64);
        const float4* bb = (const float4*)sb1;
#pragma unroll
        for (int q = 0; q < 16; q++) {
            float4 v;
            v.x = fmaxf(fmaf(ax, w0[q].x, fmaf(ay, w1[q].x, bb[q].x)), 0.f);
            v.y = fmaxf(fmaf(ax, w0[q].y, fmaf(ay, w1[q].y, bb[q].y)), 0.f);
            v.z = fmaxf(fmaf(ax, w0[q].z, fmaf(ay, w1[q].z, bb[q].z)), 0.f);
            v.w = fmaxf(fmaf(ax, w0[q].w, fmaf(ay, w1[q].w, bb[q].w)), 0.f);
            row[q] = v;
        }
    }
    __syncthreads();
    /* coalesced copy-out: block rows are contiguous in g_h1 */
    int n4 = nrows * 16;
    float4* dst = g_h1 + (size_t)blk0 * 16;
    const float4* s4 = (const float4*)sS;
    for (int i = tid; i < n4; i += 128) {
        int r = i >> 4, c = i & 15;
        dst[i] = s4[r * 17 + c];
    }
}

/* ------- fused: 64-wide gather agg + h2 = relu(C@W2+b2), transposed ------- */
__global__ __launch_bounds__(256) void k_aggCF1(const float* __restrict__ W2,
                                                const float* __restrict__ b2) {
    __shared__ float sC[64 * 65];          /* [r][ci], pad 65: conflict-free */
    __shared__ __align__(16) float sW2[4096];
    int tid = threadIdx.x;
    int t = blockIdx.y;
    for (int i = tid; i < 1024; i += 256)
        ((float4*)sW2)[i] = ((const float4*)W2)[i];

    int warp = tid >> 5, lane = tid & 31;
    int wi = blockIdx.x * 8 + warp;        /* 1250*8 = 10000 exact */

    const float4* h1t = g_h1 + (size_t)t * NN * 128;
    const float4* rn = h1t + (size_t)wi * 128 + lane;
    float sf = g_self[wi];
    float4 a0 = scale4(sf, rn[0]);
    float4 a1 = scale4(sf, rn[32]);
    float4 a2 = scale4(sf, rn[64]);
    float4 a3 = scale4(sf, rn[96]);
    int j0 = g_off[wi], j1 = g_end[wi];
    for (int j = j0; j < j1; j++) {
        int s = g_csr_src[j];
        float nr = g_csr_w[j];
        const float4* rs = h1t + (size_t)s * 128 + lane;
        fma4(a0, nr, rs[0]);
        fma4(a1, nr, rs[32]);
        fma4(a2, nr, rs[64]);
        fma4(a3, nr, rs[96]);
    }
    /* stage C tile: row r = warp*8 + b, feature ci */
    {
        int bq = lane >> 4, q = lane & 15;
        int cb = 4 * q;
        float* p0 = sC + (warp * 8 + bq    ) * 65 + cb;
        float* p1 = sC + (warp * 8 + bq + 2) * 65 + cb;
        float* p2 = sC + (warp * 8 + bq + 4) * 65 + cb;
        float* p3 = sC + (warp * 8 + bq + 6) * 65 + cb;
        p0[0] = a0.x; p0[1] = a0.y; p0[2] = a0.z; p0[3] = a0.w;
        p1[0] = a1.x; p1[1] = a1.y; p1[2] = a1.z; p1[3] = a1.w;
        p2[0] = a2.x; p2[1] = a2.y; p2[2] = a2.z; p2[3] = a2.w;
        p3[0] = a3.x; p3[1] = a3.y; p3[2] = a3.z; p3[3] = a3.w;
    }
    __syncthreads();

    /* GEMM phase: thread = (r2 = tid&31 -> rows r2, r2+32; g = tid>>5 -> 8 cos) */
    int r2 = tid & 31, g = tid >> 5;
    ull accA[4], accB[4];
#pragma unroll
    for (int k = 0; k < 4; k++) {
        float2 bb = __ldg((const float2*)b2 + g * 4 + k);
        accA[k] = pk2(bb.x, bb.y);
        accB[k] = accA[k];
    }
    const float* cA = sC + r2 * 65;
    const float* cB = sC + (r2 + 32) * 65;
#pragma unroll 4
    for (int ci = 0; ci < 64; ci++) {
        ull xA = bc2(cA[ci]);
        ull xB = bc2(cB[ci]);
        const ulonglong2* wp = (const ulonglong2*)(sW2 + ci * 64 + g * 8);
        ulonglong2 wa = wp[0], wb = wp[1];
        accA[0] = fma2(xA, wa.x, accA[0]);
        accA[1] = fma2(xA, wa.y, accA[1]);
        accA[2] = fma2(xA, wb.x, accA[2]);
        accA[3] = fma2(xA, wb.y, accA[3]);
        accB[0] = fma2(xB, wa.x, accB[0]);
        accB[1] = fma2(xB, wa.y, accB[1]);
        accB[2] = fma2(xB, wb.x, accB[2]);
        accB[3] = fma2(xB, wb.y, accB[3]);
    }
    /* store transposed: g_h2[(t*64+co)*NB + blockIdx.x*64 + r] */
    size_t nb0 = (size_t)blockIdx.x * 64;
    float* hb = g_h2 + (size_t)t * 64 * NB + nb0;
#pragma unroll
    for (int k = 0; k < 4; k++) {
        int co = g * 8 + 2 * k;
        float2 u = unp(accA[k]);
        float2 v = unp(accB[k]);
        hb[(size_t)co * NB + r2]            = fmaxf(u.x, 0.f);
        hb[(size_t)(co + 1) * NB + r2]      = fmaxf(u.y, 0.f);
        hb[(size_t)co * NB + r2 + 32]       = fmaxf(v.x, 0.f);
        hb[(size_t)(co + 1) * NB + r2 + 32] = fmaxf(v.y, 0.f);
    }
}

/* ---------------- F2: temporal convs (needed taps) + head, packed --------- */
#define F2_SMEM ((5 * 4096 + 192) * 4)
__global__ __launch_bounds__(128) void k_f2(const float* __restrict__ tc1w,
                                            const float* __restrict__ tc1b,
                                            const float* __restrict__ tc2w,
                                            const float* __restrict__ tc2b,
                                            const float* __restrict__ ow,
                                            const float* __restrict__ ob,
                                            float* __restrict__ out) {
    extern __shared__ __align__(16) float sm[];
    float* w10 = sm;            /* [ci][co] = tc1_w[co][ci][tap] */
    float* w11 = sm + 4096;
    float* w12 = sm + 8192;
    float* w20 = sm + 12288;    /* [co2][ci] = tc2_w[co2][ci][tap] */
    float* w21 = sm + 16384;
    float* tb1 = sm + 20480;
    float* tb2 = tb1 + 64;
    float* ows = tb2 + 64;
    int tid = threadIdx.x;
    for (int i = tid; i < 4096; i += 128) {
        int ci = i >> 6, co = i & 63;
        int s1 = (co * 64 + ci) * 3;
        w10[i] = tc1w[s1];
        w11[i] = tc1w[s1 + 1];
        w12[i] = tc1w[s1 + 2];
        w20[i] = tc2w[i * 3];
        w21[i] = tc2w[i * 3 + 1];
    }
    if (tid < 64) { tb1[tid] = tc1b[tid]; tb2[tid] = tc2b[tid]; ows[tid] = ow[tid]; }
    __syncthreads();
    int idx = blockIdx.x * 128 + tid;   /* b fastest: coalesced h2 reads */
    if (idx >= NB) return;
    int b = idx & 7, n = idx >> 3;

    ull a10[32], a11[32];
    const ull* tb1p = (const ull*)tb1;
#pragma unroll
    for (int p = 0; p < 32; p++) { a10[p] = tb1p[p]; a11[p] = tb1p[p]; }

    const float* hp = g_h2 + idx;       /* + (t*64+ci)*NB */
    float s9  = hp[0];
    float s10 = hp[(size_t)64 * NB];
    float s11 = hp[(size_t)128 * NB];
    for (int ci = 0; ci < 64; ci++) {
        float n9 = 0.f, n10 = 0.f, n11 = 0.f;
        if (ci < 63) {   /* prefetch next plane */
            n9  = hp[(size_t)(ci + 1) * NB];
            n10 = hp[(size_t)(64 + ci + 1) * NB];
            n11 = hp[(size_t)(128 + ci + 1) * NB];
        }
        ull b9 = bc2(s9), b10 = bc2(s10), b11 = bc2(s11);
        const ulonglong2* p0 = (const ulonglong2*)(w10 + ci * 64);
        const ulonglong2* p1 = (const ulonglong2*)(w11 + ci * 64);
        const ulonglong2* p2 = (const ulonglong2*)(w12 + ci * 64);
#pragma unroll
        for (int q = 0; q < 16; q++) {
            ulonglong2 t0 = p0[q], t1 = p1[q], t2 = p2[q];
            a10[2 * q]     = fma2(b9,  t0.x, a10[2 * q]);
            a10[2 * q]     = fma2(b10, t1.x, a10[2 * q]);
            a10[2 * q]     = fma2(b11, t2.x, a10[2 * q]);
            a10[2 * q + 1] = fma2(b9,  t0.y, a10[2 * q + 1]);
            a10[2 * q + 1] = fma2(b10, t1.y, a10[2 * q + 1]);
            a10[2 * q + 1] = fma2(b11, t2.y, a10[2 * q + 1]);
            a11[2 * q]     = fma2(b10, t0.x, a11[2 * q]);
            a11[2 * q]     = fma2(b11, t1.x, a11[2 * q]);
            a11[2 * q + 1] = fma2(b10, t0.y, a11[2 * q + 1]);
            a11[2 * q + 1] = fma2(b11, t1.y, a11[2 * q + 1]);
        }
        s9 = n9; s10 = n10; s11 = n11;
    }
#pragma unroll
    for (int p = 0; p < 32; p++) {
        float2 u = unp(a10[p]);
        a10[p] = pk2(fmaxf(u.x, 0.f), fmaxf(u.y, 0.f));
        float2 v = unp(a11[p]);
        a11[p] = pk2(fmaxf(v.x, 0.f), fmaxf(v.y, 0.f));
    }

    float acc = 0.f;
    for (int co = 0; co < 64; co++) {
        ull sp0 = 0, sp1 = 0, sp2 = 0, sp3 = 0;
        const ulonglong2* pa = (const ulonglong2*)(w20 + co * 64);
        const ulonglong2* pb = (const ulonglong2*)(w21 + co * 64);
#pragma unroll
        for (int q = 0; q < 16; q++) {
            ulonglong2 wa = pa[q], wb = pb[q];
            sp0 = fma2(a10[2 * q],     wa.x, sp0);
            sp1 = fma2(a10[2 * q + 1], wa.y, sp1);
            sp2 = fma2(a11[2 * q],     wb.x, sp2);
            sp3 = fma2(a11[2 * q + 1], wb.y, sp3);
        }
        float2 u0 = unp(sp0), u1 = unp(sp1), u2 = unp(sp2), u3 = unp(sp3);
        float s = tb2[co] + ((u0.x + u0.y) + (u1.x + u1.y))
                          + ((u2.x + u2.y) + (u3.x + u3.y));
        acc = fmaf(fmaxf(s, 0.f), ows[co], acc);
    }
    out[b * NN + n] = acc + ob[0];
}

/* ---------------- launch ---------------- */
extern "C" void kernel_launch(void* const* d_in, const int* in_sizes, int n_in,
                              void* d_out, int out_size) {
    const float* X    = (const float*)d_in[0];
    const int*   ei   = (const int*)d_in[1];
    const float* ew   = (const float*)d_in[2];
    const float* W1   = (const float*)d_in[3];
    const float* b1   = (const float*)d_in[4];
    const float* W2   = (const float*)d_in[5];
    const float* b2   = (const float*)d_in[6];
    const float* tc1w = (const float*)d_in[7];
    const float* tc1b = (const float*)d_in[8];
    const float* tc2w = (const float*)d_in[9];
    const float* tc2b = (const float*)d_in[10];
    const float* ow   = (const float*)d_in[11];
    const float* ob   = (const float*)d_in[12];
    float* out = (float*)d_out;

    cudaFuncSetAttribute(k_f2, cudaFuncAttributeMaxDynamicSharedMemorySize, F2_SMEM);

    k_zero<<<(NN + 255) / 256, 256>>>();
    k_deg<<<(EE + 255) / 256, 256>>>(ei, ew);
    k_dinv<<<(NN + 255) / 256, 256>>>();
    k_fill<<<(EE + 255) / 256, 256>>>(ei, ew);
    k_aggAH1<<<(ROWS + 127) / 128, 128>>>(X, W1, b1);
    dim3 gC(NN / 8, TS);
    k_aggCF1<<<gC, 256>>>(W2, b2);
    k_f2<<<(NB + 127) / 128, 128, F2_SMEM>>>(tc1w, tc1b, tc2w, tc2b, ow, ob, out);
}

// round 5
// speedup vs baseline: 1.5873x; 1.1251x over previous
#include <cuda_runtime.h>
#include <cuda_fp16.h>

#define NN 10000
#define EE 160000
#define BB 8
#define TT 12
#define HH 64
#define TS 3
#define T0 9
#define ROWS (TS*NN*BB)   /* 240000 rows of 64 features */
#define NB  (BB*NN)       /* 80000 (n,b) pairs per (t,ci) plane in g_h2 */

typedef unsigned long long ull;
typedef unsigned int uint;

/* ---------------- device scratch (no allocs allowed) ---------------- */
__device__ float  g_deg[NN];
__device__ float  g_self[NN];
__device__ float  g_dinv[NN];
__device__ int    g_cnt[NN];        /* histogram, then CSR fill cursor */
__device__ int    g_off[NN];
__device__ int    g_end[NN];
__device__ int    g_alloc;
__device__ ull    g_csr[EE];        /* packed (src:int low, w:float high) */
__device__ uint4  g_h1h[TS * NN * 64];  /* fp16 h1: [t][n][b][64]  30.7MB, 64 uint4/row */
__device__ float  g_h2[TS * 64 * NB];   /* relu(agg(h1)@W2+b2) [t][co][n*8+b] 61.4MB */

/* ---------------- packed f32x2 helpers ---------------- */
__device__ __forceinline__ ull fma2(ull a, ull b, ull c) {
    ull d;
    asm("fma.rn.f32x2 %0, %1, %2, %3;" : "=l"(d) : "l"(a), "l"(b), "l"(c));
    return d;
}
__device__ __forceinline__ ull bc2(float s) {
    ull r;
    asm("mov.b64 %0, {%1, %1};" : "=l"(r) : "r"(__float_as_uint(s)));
    return r;
}
__device__ __forceinline__ float2 unp(ull v) {
    unsigned lo, hi;
    asm("mov.b64 {%0, %1}, %2;" : "=r"(lo), "=r"(hi) : "l"(v));
    return make_float2(__uint_as_float(lo), __uint_as_float(hi));
}
__device__ __forceinline__ ull pk2(float a, float b) {
    ull r;
    asm("mov.b64 %0, {%1, %2};" : "=l"(r) : "r"(__float_as_uint(a)), "r"(__float_as_uint(b)));
    return r;
}

/* ---------------- graph preprocessing ---------------- */
__global__ void k_zero() {
    int i = blockIdx.x * blockDim.x + threadIdx.x;
    if (i < NN) { g_deg[i] = 0.f; g_cnt[i] = 0; }
    if (i == 0) g_alloc = 0;
}

__global__ void k_deg(const int* __restrict__ ei, const float* __restrict__ w) {
    int e = blockIdx.x * blockDim.x + threadIdx.x;
    if (e >= EE) return;
    int d = ei[EE + e];
    atomicAdd(&g_deg[d], w[e]);
    atomicAdd(&g_cnt[d], 1);
}

/* dinv + CSR segment allocation (order-free: no prefix scan needed) */
__global__ void k_dinv() {
    int i = blockIdx.x * blockDim.x + threadIdx.x;
    int lane = threadIdx.x & 31;
    int valid = (i < NN);
    int c = valid ? g_cnt[i] : 0;
    int incl = c;
#pragma unroll
    for (int d = 1; d < 32; d <<= 1) {
        int v = __shfl_up_sync(0xffffffffu, incl, d);
        if (lane >= d) incl += v;
    }
    int wtot = __shfl_sync(0xffffffffu, incl, 31);
    int base = 0;
    if (lane == 31 && wtot > 0) base = atomicAdd(&g_alloc, wtot);
    base = __shfl_sync(0xffffffffu, base, 31);
    if (!valid) return;
    int off = base + incl - c;
    g_off[i] = off;
    g_end[i] = off + c;
    g_cnt[i] = off;                       /* fill cursor */
    float dv = rsqrtf(g_deg[i] + 1.0f);   /* self-loop weight 1 => deg>0 */
    g_dinv[i] = dv;
    g_self[i] = dv * dv;
}

__global__ void k_fill(const int* __restrict__ ei, const float* __restrict__ w) {
    int e = blockIdx.x * blockDim.x + threadIdx.x;
    if (e >= EE) return;
    int s = ei[e], d = ei[EE + e];
    float nr = g_dinv[s] * w[e] * g_dinv[d];
    int p = atomicAdd(&g_cnt[d], 1);
    g_csr[p] = ((ull)__float_as_uint(nr) << 32) | (uint)s;
}

/* ------- fused stage A: 2-wide agg of X + h1 = relu(A@W1+b1) -> fp16 ------ */
__global__ __launch_bounds__(128) void k_aggAH1(const float* __restrict__ X,
                                                const float* __restrict__ W1,
                                                const float* __restrict__ b1) {
    __shared__ __align__(16) float sW1[128];
    __shared__ __align__(16) float sb1[64];
    int tid = threadIdx.x;
    if (tid < 128) sW1[tid] = W1[tid];
    if (tid < 64)  sb1[tid] = b1[tid];
    __syncthreads();

    int idx = blockIdx.x * 128 + tid;
    if (idx >= ROWS) return;
    int b = idx & 7;
    int nt = idx >> 3;
    int n = nt % NN;
    int t = nt / NN;
    const float2* base = (const float2*)X + (size_t)(b * TT + T0 + t) * NN;
    float2 x = base[n];
    float sf = g_self[n];
    float ax = sf * x.x, ay = sf * x.y;
    int j0 = g_off[n], j1 = g_end[n];
    for (int j = j0; j < j1; j++) {
        ull e = g_csr[j];
        int s = (int)(e & 0xffffffffu);
        float nr = __uint_as_float((uint)(e >> 32));
        float2 xs = base[s];
        ax = fmaf(nr, xs.x, ax);
        ay = fmaf(nr, xs.y, ay);
    }
    /* h1 row = relu(ax*W1[0] + ay*W1[1] + b1) -> fp16, 64 halves contiguous */
    const float4* w0 = (const float4*)sW1;
    const float4* w1 = (const float4*)(sW1 + 64);
    const float4* bb = (const float4*)sb1;
    uint4* dst = g_h1h + (size_t)idx * 8;
#pragma unroll
    for (int q8 = 0; q8 < 8; q8++) {
        uint4 o;
        uint* op = (uint*)&o;
#pragma unroll
        for (int h = 0; h < 4; h++) {
            int q = q8 * 2 + (h >> 1);
            float4 W0 = w0[q], W1v = w1[q], Bv = bb[q];
            float v0, v1;
            if ((h & 1) == 0) {
                v0 = fmaxf(fmaf(ax, W0.x, fmaf(ay, W1v.x, Bv.x)), 0.f);
                v1 = fmaxf(fmaf(ax, W0.y, fmaf(ay, W1v.y, Bv.y)), 0.f);
            } else {
                v0 = fmaxf(fmaf(ax, W0.z, fmaf(ay, W1v.z, Bv.z)), 0.f);
                v1 = fmaxf(fmaf(ax, W0.w, fmaf(ay, W1v.w, Bv.w)), 0.f);
            }
            __half2 hh = __floats2half2_rn(v0, v1);
            op[h] = *(uint*)&hh;
        }
        dst[q8] = o;
    }
}

/* ------- fused: 64-wide fp16 gather agg + h2 = relu(C@W2+b2), transposed -- */
__global__ __launch_bounds__(256) void k_aggCF1(const float* __restrict__ W2,
                                                const float* __restrict__ b2) {
    __shared__ float sC[64 * 65];          /* [r][ci], pad 65 */
    __shared__ __align__(16) float sW2[4096];
    int tid = threadIdx.x;
    int t = blockIdx.y;
    for (int i = tid; i < 1024; i += 256)
        ((float4*)sW2)[i] = ((const float4*)W2)[i];

    int warp = tid >> 5, lane = tid & 31;
    int wi = blockIdx.x * 8 + warp;        /* 1250*8 = 10000 exact */

    const uint4* h1t = g_h1h + (size_t)t * NN * 64;
    const uint4* rn = h1t + (size_t)wi * 64 + lane;   /* rn[0], rn[32] */
    float sf = g_self[wi];
    float aA[8], aB[8];
    {
        uint4 v0 = rn[0], v1 = rn[32];
        const __half2* p0 = (const __half2*)&v0;
        const __half2* p1 = (const __half2*)&v1;
#pragma unroll
        for (int k = 0; k < 4; k++) {
            float2 f0 = __half22float2(p0[k]);
            float2 f1 = __half22float2(p1[k]);
            aA[2 * k]     = sf * f0.x;
            aA[2 * k + 1] = sf * f0.y;
            aB[2 * k]     = sf * f1.x;
            aB[2 * k + 1] = sf * f1.y;
        }
    }
    int j0 = g_off[wi], j1 = g_end[wi];
    for (int j = j0; j < j1; j++) {
        ull e = g_csr[j];
        int s = (int)(e & 0xffffffffu);
        float nr = __uint_as_float((uint)(e >> 32));
        const uint4* rs = h1t + (size_t)s * 64 + lane;
        uint4 v0 = rs[0], v1 = rs[32];
        const __half2* p0 = (const __half2*)&v0;
        const __half2* p1 = (const __half2*)&v1;
#pragma unroll
        for (int k = 0; k < 4; k++) {
            float2 f0 = __half22float2(p0[k]);
            float2 f1 = __half22float2(p1[k]);
            aA[2 * k]     = fmaf(nr, f0.x, aA[2 * k]);
            aA[2 * k + 1] = fmaf(nr, f0.y, aA[2 * k + 1]);
            aB[2 * k]     = fmaf(nr, f1.x, aB[2 * k]);
            aB[2 * k + 1] = fmaf(nr, f1.y, aB[2 * k + 1]);
        }
    }
    /* stage C tile: lane holds p = 8*lane+k (b = lane>>3, f = (lane&7)*8+k)
       and p+256 (b+4) */
    {
        int bl = lane >> 3;
        int f0 = (lane & 7) * 8;
        float* pA = sC + (warp * 8 + bl) * 65 + f0;
        float* pB = sC + (warp * 8 + 4 + bl) * 65 + f0;
#pragma unroll
        for (int k = 0; k < 8; k++) { pA[k] = aA[k]; pB[k] = aB[k]; }
    }
    __syncthreads();

    /* GEMM: thread = (r2 = tid&31 -> rows r2, r2+32; g = tid>>5 -> 8 cos) */
    int r2 = tid & 31, g = tid >> 5;
    ull accA[4], accB[4];
#pragma unroll
    for (int k = 0; k < 4; k++) {
        float2 bbv = __ldg((const float2*)b2 + g * 4 + k);
        accA[k] = pk2(bbv.x, bbv.y);
        accB[k] = accA[k];
    }
    const float* cA = sC + r2 * 65;
    const float* cB = sC + (r2 + 32) * 65;
#pragma unroll 4
    for (int ci = 0; ci < 64; ci++) {
        ull xA = bc2(cA[ci]);
        ull xB = bc2(cB[ci]);
        const ulonglong2* wp = (const ulonglong2*)(sW2 + ci * 64 + g * 8);
        ulonglong2 wa = wp[0], wb = wp[1];
        accA[0] = fma2(xA, wa.x, accA[0]);
        accA[1] = fma2(xA, wa.y, accA[1]);
        accA[2] = fma2(xA, wb.x, accA[2]);
        accA[3] = fma2(xA, wb.y, accA[3]);
        accB[0] = fma2(xB, wa.x, accB[0]);
        accB[1] = fma2(xB, wa.y, accB[1]);
        accB[2] = fma2(xB, wb.x, accB[2]);
        accB[3] = fma2(xB, wb.y, accB[3]);
    }
    /* store transposed: g_h2[(t*64+co)*NB + blockIdx.x*64 + r] */
    size_t nb0 = (size_t)blockIdx.x * 64;
    float* hb = g_h2 + (size_t)t * 64 * NB + nb0;
#pragma unroll
    for (int k = 0; k < 4; k++) {
        int co = g * 8 + 2 * k;
        float2 u = unp(accA[k]);
        float2 v = unp(accB[k]);
        hb[(size_t)co * NB + r2]            = fmaxf(u.x, 0.f);
        hb[(size_t)(co + 1) * NB + r2]      = fmaxf(u.y, 0.f);
        hb[(size_t)co * NB + r2 + 32]       = fmaxf(v.x, 0.f);
        hb[(size_t)(co + 1) * NB + r2 + 32] = fmaxf(v.y, 0.f);
    }
}

/* ---------------- F2: temporal convs (needed taps) + head, packed --------- */
#define F2_SMEM ((5 * 4096 + 192) * 4)
__global__ __launch_bounds__(128) void k_f2(const float* __restrict__ tc1w,
                                            const float* __restrict__ tc1b,
                                            const float* __restrict__ tc2w,
                                            const float* __restrict__ tc2b,
                                            const float* __restrict__ ow,
                                            const float* __restrict__ ob,
                                            float* __restrict__ out) {
    extern __shared__ __align__(16) float sm[];
    float* w10 = sm;            /* [ci][co] = tc1_w[co][ci][tap] */
    float* w11 = sm + 4096;
    float* w12 = sm + 8192;
    float* w20 = sm + 12288;    /* [co2][ci] = tc2_w[co2][ci][tap] */
    float* w21 = sm + 16384;
    float* tb1 = sm + 20480;
    float* tb2 = tb1 + 64;
    float* ows = tb2 + 64;
    int tid = threadIdx.x;
    for (int i = tid; i < 4096; i += 128) {
        int ci = i >> 6, co = i & 63;
        int s1 = (co * 64 + ci) * 3;
        w10[i] = tc1w[s1];
        w11[i] = tc1w[s1 + 1];
        w12[i] = tc1w[s1 + 2];
        w20[i] = tc2w[i * 3];
        w21[i] = tc2w[i * 3 + 1];
    }
    if (tid < 64) { tb1[tid] = tc1b[tid]; tb2[tid] = tc2b[tid]; ows[tid] = ow[tid]; }
    __syncthreads();
    int idx = blockIdx.x * 128 + tid;   /* b fastest: coalesced h2 reads */
    if (idx >= NB) return;
    int b = idx & 7, n = idx >> 3;

    ull a10[32], a11[32];
    const ull* tb1p = (const ull*)tb1;
#pragma unroll
    for (int p = 0; p < 32; p++) { a10[p] = tb1p[p]; a11[p] = tb1p[p]; }

    const float* hp = g_h2 + idx;       /* + (t*64+ci)*NB */
    float s9  = hp[0];
    float s10 = hp[(size_t)64 * NB];
    float s11 = hp[(size_t)128 * NB];
    for (int ci = 0; ci < 64; ci++) {
        float n9 = 0.f, n10 = 0.f, n11 = 0.f;
        if (ci < 63) {   /* prefetch next plane */
            n9  = hp[(size_t)(ci + 1) * NB];
            n10 = hp[(size_t)(64 + ci + 1) * NB];
            n11 = hp[(size_t)(128 + ci + 1) * NB];
        }
        ull b9 = bc2(s9), b10 = bc2(s10), b11 = bc2(s11);
        const ulonglong2* p0 = (const ulonglong2*)(w10 + ci * 64);
        const ulonglong2* p1 = (const ulonglong2*)(w11 + ci * 64);
        const ulonglong2* p2 = (const ulonglong2*)(w12 + ci * 64);
#pragma unroll
        for (int q = 0; q < 16; q++) {
            ulonglong2 t0 = p0[q], t1 = p1[q], t2 = p2[q];
            a10[2 * q]     = fma2(b9,  t0.x, a10[2 * q]);
            a10[2 * q]     = fma2(b10, t1.x, a10[2 * q]);
            a10[2 * q]     = fma2(b11, t2.x, a10[2 * q]);
            a10[2 * q + 1] = fma2(b9,  t0.y, a10[2 * q + 1]);
            a10[2 * q + 1] = fma2(b10, t1.y, a10[2 * q + 1]);
            a10[2 * q + 1] = fma2(b11, t2.y, a10[2 * q + 1]);
            a11[2 * q]     = fma2(b10, t0.x, a11[2 * q]);
            a11[2 * q]     = fma2(b11, t1.x, a11[2 * q]);
            a11[2 * q + 1] = fma2(b10, t0.y, a11[2 * q + 1]);
            a11[2 * q + 1] = fma2(b11, t1.y, a11[2 * q + 1]);
        }
        s9 = n9; s10 = n10; s11 = n11;
    }
#pragma unroll
    for (int p = 0; p < 32; p++) {
        float2 u = unp(a10[p]);
        a10[p] = pk2(fmaxf(u.x, 0.f), fmaxf(u.y, 0.f));
        float2 v = unp(a11[p]);
        a11[p] = pk2(fmaxf(v.x, 0.f), fmaxf(v.y, 0.f));
    }

    float acc = 0.f;
    for (int co = 0; co < 64; co++) {
        ull sp0 = 0, sp1 = 0, sp2 = 0, sp3 = 0;
        const ulonglong2* pa = (const ulonglong2*)(w20 + co * 64);
        const ulonglong2* pb = (const ulonglong2*)(w21 + co * 64);
#pragma unroll
        for (int q = 0; q < 16; q++) {
            ulonglong2 wa = pa[q], wb = pb[q];
            sp0 = fma2(a10[2 * q],     wa.x, sp0);
            sp1 = fma2(a10[2 * q + 1], wa.y, sp1);
            sp2 = fma2(a11[2 * q],     wb.x, sp2);
            sp3 = fma2(a11[2 * q + 1], wb.y, sp3);
        }
        float2 u0 = unp(sp0), u1 = unp(sp1), u2 = unp(sp2), u3 = unp(sp3);
        float s = tb2[co] + ((u0.x + u0.y) + (u1.x + u1.y))
                          + ((u2.x + u2.y) + (u3.x + u3.y));
        acc = fmaf(fmaxf(s, 0.f), ows[co], acc);
    }
    out[b * NN + n] = acc + ob[0];
}

/* ---------------- launch ---------------- */
extern "C" void kernel_launch(void* const* d_in, const int* in_sizes, int n_in,
                              void* d_out, int out_size) {
    const float* X    = (const float*)d_in[0];
    const int*   ei   = (const int*)d_in[1];
    const float* ew   = (const float*)d_in[2];
    const float* W1   = (const float*)d_in[3];
    const float* b1   = (const float*)d_in[4];
    const float* W2   = (const float*)d_in[5];
    const float* b2   = (const float*)d_in[6];
    const float* tc1w = (const float*)d_in[7];
    const float* tc1b = (const float*)d_in[8];
    const float* tc2w = (const float*)d_in[9];
    const float* tc2b = (const float*)d_in[10];
    const float* ow   = (const float*)d_in[11];
    const float* ob   = (const float*)d_in[12];
    float* out = (float*)d_out;

    cudaFuncSetAttribute(k_f2, cudaFuncAttributeMaxDynamicSharedMemorySize, F2_SMEM);

    k_zero<<<(NN + 255) / 256, 256>>>();
    k_deg<<<(EE + 255) / 256, 256>>>(ei, ew);
    k_dinv<<<(NN + 255) / 256, 256>>>();
    k_fill<<<(EE + 255) / 256, 256>>>(ei, ew);
    k_aggAH1<<<(ROWS + 127) / 128, 128>>>(X, W1, b1);
    dim3 gC(NN / 8, TS);
    k_aggCF1<<<gC, 256>>>(W2, b2);
    k_f2<<<(NB + 127) / 128, 128, F2_SMEM>>>(tc1w, tc1b, tc2w, tc2b, ow, ob, out);
}

// round 6
// speedup vs baseline: 1.6782x; 1.0573x over previous
#include <cuda_runtime.h>
#include <cuda_fp16.h>

#define NN 10000
#define EE 160000
#define BB 8
#define TT 12
#define HH 64
#define TS 3
#define T0 9
#define ROWS (TS*NN*BB)   /* 240000 rows of 64 features */
#define NB  (BB*NN)       /* 80000 (n,b) pairs per (t,ci) plane in g_h2h */

typedef unsigned long long ull;
typedef unsigned int uint;

/* ---------------- device scratch (no allocs allowed) ---------------- */
__device__ float  g_deg[NN];
__device__ float  g_self[NN];
__device__ float  g_dinv[NN];
__device__ int    g_cnt[NN];        /* histogram, then CSR fill cursor */
__device__ int    g_off[NN];
__device__ int    g_end[NN];
__device__ int    g_alloc;
__device__ ull    g_csr[EE];        /* packed (src:int low, w:float high) */
__device__ uint4  g_h1h[TS * NN * 64];  /* fp16 h1: [t][n][b][64]  30.7MB */
__device__ __half g_h2h[TS * 64 * NB];  /* fp16 h2: [t][co][n*8+b] 30.7MB */

/* ---------------- packed f32x2 helpers ---------------- */
__device__ __forceinline__ ull fma2(ull a, ull b, ull c) {
    ull d;
    asm("fma.rn.f32x2 %0, %1, %2, %3;" : "=l"(d) : "l"(a), "l"(b), "l"(c));
    return d;
}
__device__ __forceinline__ ull bc2(float s) {
    ull r;
    asm("mov.b64 %0, {%1, %1};" : "=l"(r) : "r"(__float_as_uint(s)));
    return r;
}
__device__ __forceinline__ float2 unp(ull v) {
    unsigned lo, hi;
    asm("mov.b64 {%0, %1}, %2;" : "=r"(lo), "=r"(hi) : "l"(v));
    return make_float2(__uint_as_float(lo), __uint_as_float(hi));
}
__device__ __forceinline__ ull pk2(float a, float b) {
    ull r;
    asm("mov.b64 %0, {%1, %2};" : "=l"(r) : "r"(__float_as_uint(a)), "r"(__float_as_uint(b)));
    return r;
}

/* ---------------- graph preprocessing ---------------- */
__global__ void k_zero() {
    int i = blockIdx.x * blockDim.x + threadIdx.x;
    if (i < NN) { g_deg[i] = 0.f; g_cnt[i] = 0; }
    if (i == 0) g_alloc = 0;
}

__global__ void k_deg(const int* __restrict__ ei, const float* __restrict__ w) {
    int e = blockIdx.x * blockDim.x + threadIdx.x;
    if (e >= EE) return;
    int d = ei[EE + e];
    float wv = w[e];
    atomicAdd(&g_deg[d], wv);
    atomicAdd(&g_cnt[d], 1);
}

/* dinv + CSR segment allocation (order-free: no prefix scan needed) */
__global__ void k_dinv() {
    int i = blockIdx.x * blockDim.x + threadIdx.x;
    int lane = threadIdx.x & 31;
    int valid = (i < NN);
    int c = valid ? g_cnt[i] : 0;
    int incl = c;
#pragma unroll
    for (int d = 1; d < 32; d <<= 1) {
        int v = __shfl_up_sync(0xffffffffu, incl, d);
        if (lane >= d) incl += v;
    }
    int wtot = __shfl_sync(0xffffffffu, incl, 31);
    int base = 0;
    if (lane == 31 && wtot > 0) base = atomicAdd(&g_alloc, wtot);
    base = __shfl_sync(0xffffffffu, base, 31);
    if (!valid) return;
    int off = base + incl - c;
    g_off[i] = off;
    g_end[i] = off + c;
    g_cnt[i] = off;                       /* fill cursor */
    float dv = rsqrtf(g_deg[i] + 1.0f);   /* self-loop weight 1 => deg>0 */
    g_dinv[i] = dv;
    g_self[i] = dv * dv;
}

__global__ void k_fill(const int* __restrict__ ei, const float* __restrict__ w) {
    int e = blockIdx.x * blockDim.x + threadIdx.x;
    if (e >= EE) return;
    int s = ei[e], d = ei[EE + e];
    float wv = w[e];
    float nr = g_dinv[s] * wv * g_dinv[d];
    int p = atomicAdd(&g_cnt[d], 1);
    g_csr[p] = ((ull)__float_as_uint(nr) << 32) | (uint)s;
}

/* ------- fused stage A: 2-wide agg of X + h1 = relu(A@W1+b1) -> fp16 ------ */
__global__ __launch_bounds__(256) void k_aggAH1(const float* __restrict__ X,
                                                const float* __restrict__ W1,
                                                const float* __restrict__ b1) {
    __shared__ __align__(16) float sW1[128];
    __shared__ __align__(16) float sb1[64];
    int tid = threadIdx.x;
    if (tid < 128) sW1[tid] = W1[tid];
    if (tid < 64)  sb1[tid] = b1[tid];
    __syncthreads();

    int idx = blockIdx.x * 256 + tid;
    if (idx >= ROWS) return;
    int b = idx & 7;
    int nt = idx >> 3;
    int n = nt % NN;
    int t = nt / NN;
    const float2* base = (const float2*)X + (size_t)(b * TT + T0 + t) * NN;
    float2 x = base[n];
    float sf = g_self[n];
    float ax = sf * x.x, ay = sf * x.y;
    int j = g_off[n], j1 = g_end[n];
    /* unroll by 2 with batched loads for MLP */
    for (; j + 2 <= j1; j += 2) {
        ull e0 = g_csr[j], e1 = g_csr[j + 1];
        int s0 = (int)(e0 & 0xffffffffu);
        int s1 = (int)(e1 & 0xffffffffu);
        float2 xs0 = base[s0];
        float2 xs1 = base[s1];
        float nr0 = __uint_as_float((uint)(e0 >> 32));
        float nr1 = __uint_as_float((uint)(e1 >> 32));
        ax = fmaf(nr0, xs0.x, ax);
        ay = fmaf(nr0, xs0.y, ay);
        ax = fmaf(nr1, xs1.x, ax);
        ay = fmaf(nr1, xs1.y, ay);
    }
    if (j < j1) {
        ull e = g_csr[j];
        int s = (int)(e & 0xffffffffu);
        float nr = __uint_as_float((uint)(e >> 32));
        float2 xs = base[s];
        ax = fmaf(nr, xs.x, ax);
        ay = fmaf(nr, xs.y, ay);
    }
    /* h1 row = relu(ax*W1[0] + ay*W1[1] + b1) -> fp16 */
    const float4* w0 = (const float4*)sW1;
    const float4* w1 = (const float4*)(sW1 + 64);
    const float4* bb = (const float4*)sb1;
    uint4* dst = g_h1h + (size_t)idx * 8;
#pragma unroll
    for (int q8 = 0; q8 < 8; q8++) {
        uint4 o;
        uint* op = (uint*)&o;
#pragma unroll
        for (int h = 0; h < 4; h++) {
            int q = q8 * 2 + (h >> 1);
            float4 W0 = w0[q], W1v = w1[q], Bv = bb[q];
            float v0, v1;
            if ((h & 1) == 0) {
                v0 = fmaxf(fmaf(ax, W0.x, fmaf(ay, W1v.x, Bv.x)), 0.f);
                v1 = fmaxf(fmaf(ax, W0.y, fmaf(ay, W1v.y, Bv.y)), 0.f);
            } else {
                v0 = fmaxf(fmaf(ax, W0.z, fmaf(ay, W1v.z, Bv.z)), 0.f);
                v1 = fmaxf(fmaf(ax, W0.w, fmaf(ay, W1v.w, Bv.w)), 0.f);
            }
            __half2 hh = __floats2half2_rn(v0, v1);
            op[h] = *(uint*)&hh;
        }
        dst[q8] = o;
    }
}

/* ------- fused: 64-wide fp16 gather agg + h2 = relu(C@W2+b2) -> fp16 ------ */
__device__ __forceinline__ void acc_row(const uint4* h1t, int s, int lane,
                                        float nr, float* aA, float* aB) {
    const uint4* rs = h1t + (size_t)s * 64 + lane;
    uint4 v0 = rs[0], v1 = rs[32];
    const __half2* p0 = (const __half2*)&v0;
    const __half2* p1 = (const __half2*)&v1;
#pragma unroll
    for (int k = 0; k < 4; k++) {
        float2 f0 = __half22float2(p0[k]);
        float2 f1 = __half22float2(p1[k]);
        aA[2 * k]     = fmaf(nr, f0.x, aA[2 * k]);
        aA[2 * k + 1] = fmaf(nr, f0.y, aA[2 * k + 1]);
        aB[2 * k]     = fmaf(nr, f1.x, aB[2 * k]);
        aB[2 * k + 1] = fmaf(nr, f1.y, aB[2 * k + 1]);
    }
}

__global__ __launch_bounds__(256) void k_aggCF1(const float* __restrict__ W2,
                                                const float* __restrict__ b2) {
    __shared__ float sC[64 * 65];          /* [r][ci], pad 65 */
    __shared__ __align__(16) float sW2[4096];
    int tid = threadIdx.x;
    int t = blockIdx.y;
    for (int i = tid; i < 1024; i += 256)
        ((float4*)sW2)[i] = ((const float4*)W2)[i];

    int warp = tid >> 5, lane = tid & 31;
    int wi = blockIdx.x * 8 + warp;        /* 1250*8 = 10000 exact */

    const uint4* h1t = g_h1h + (size_t)t * NN * 64;
    const uint4* rn = h1t + (size_t)wi * 64 + lane;
    float sf = g_self[wi];
    float aA[8], aB[8];
    {
        uint4 v0 = rn[0], v1 = rn[32];
        const __half2* p0 = (const __half2*)&v0;
        const __half2* p1 = (const __half2*)&v1;
#pragma unroll
        for (int k = 0; k < 4; k++) {
            float2 f0 = __half22float2(p0[k]);
            float2 f1 = __half22float2(p1[k]);
            aA[2 * k]     = sf * f0.x;
            aA[2 * k + 1] = sf * f0.y;
            aB[2 * k]     = sf * f1.x;
            aB[2 * k + 1] = sf * f1.y;
        }
    }
    int j = g_off[wi], j1 = g_end[wi];
    for (; j + 2 <= j1; j += 2) {
        ull e0 = g_csr[j], e1 = g_csr[j + 1];
        int s0 = (int)(e0 & 0xffffffffu);
        int s1 = (int)(e1 & 0xffffffffu);
        float nr0 = __uint_as_float((uint)(e0 >> 32));
        float nr1 = __uint_as_float((uint)(e1 >> 32));
        /* batch the 4 LDG.128s before accumulating */
        const uint4* rs0 = h1t + (size_t)s0 * 64 + lane;
        const uint4* rs1 = h1t + (size_t)s1 * 64 + lane;
        uint4 a0 = rs0[0], a1 = rs0[32];
        uint4 b0 = rs1[0], b1 = rs1[32];
        {
            const __half2* p0 = (const __half2*)&a0;
            const __half2* p1 = (const __half2*)&a1;
            const __half2* q0 = (const __half2*)&b0;
            const __half2* q1 = (const __half2*)&b1;
#pragma unroll
            for (int k = 0; k < 4; k++) {
                float2 f0 = __half22float2(p0[k]);
                float2 f1 = __half22float2(p1[k]);
                float2 g0 = __half22float2(q0[k]);
                float2 g1 = __half22float2(q1[k]);
                aA[2 * k]     = fmaf(nr0, f0.x, aA[2 * k]);
                aA[2 * k + 1] = fmaf(nr0, f0.y, aA[2 * k + 1]);
                aB[2 * k]     = fmaf(nr0, f1.x, aB[2 * k]);
                aB[2 * k + 1] = fmaf(nr0, f1.y, aB[2 * k + 1]);
                aA[2 * k]     = fmaf(nr1, g0.x, aA[2 * k]);
                aA[2 * k + 1] = fmaf(nr1, g0.y, aA[2 * k + 1]);
                aB[2 * k]     = fmaf(nr1, g1.x, aB[2 * k]);
                aB[2 * k + 1] = fmaf(nr1, g1.y, aB[2 * k + 1]);
            }
        }
    }
    if (j < j1) {
        ull e = g_csr[j];
        int s = (int)(e & 0xffffffffu);
        float nr = __uint_as_float((uint)(e >> 32));
        acc_row(h1t, s, lane, nr, aA, aB);
    }
    /* stage C tile: lane holds b = lane>>3, f = (lane&7)*8 .. +7 (and b+4) */
    {
        int bl = lane >> 3;
        int f0 = (lane & 7) * 8;
        float* pA = sC + (warp * 8 + bl) * 65 + f0;
        float* pB = sC + (warp * 8 + 4 + bl) * 65 + f0;
#pragma unroll
        for (int k = 0; k < 8; k++) { pA[k] = aA[k]; pB[k] = aB[k]; }
    }
    __syncthreads();

    /* GEMM: thread = (r2 = tid&31 -> rows r2, r2+32; g = tid>>5 -> 8 cos) */
    int r2 = tid & 31, g = tid >> 5;
    ull accA[4], accB[4];
#pragma unroll
    for (int k = 0; k < 4; k++) {
        float2 bbv = __ldg((const float2*)b2 + g * 4 + k);
        accA[k] = pk2(bbv.x, bbv.y);
        accB[k] = accA[k];
    }
    const float* cA = sC + r2 * 65;
    const float* cB = sC + (r2 + 32) * 65;
#pragma unroll 4
    for (int ci = 0; ci < 64; ci++) {
        ull xA = bc2(cA[ci]);
        ull xB = bc2(cB[ci]);
        const ulonglong2* wp = (const ulonglong2*)(sW2 + ci * 64 + g * 8);
        ulonglong2 wa = wp[0], wb = wp[1];
        accA[0] = fma2(xA, wa.x, accA[0]);
        accA[1] = fma2(xA, wa.y, accA[1]);
        accA[2] = fma2(xA, wb.x, accA[2]);
        accA[3] = fma2(xA, wb.y, accA[3]);
        accB[0] = fma2(xB, wa.x, accB[0]);
        accB[1] = fma2(xB, wa.y, accB[1]);
        accB[2] = fma2(xB, wb.x, accB[2]);
        accB[3] = fma2(xB, wb.y, accB[3]);
    }
    /* store fp16 transposed: g_h2h[(t*64+co)*NB + blockIdx.x*64 + r] */
    size_t nb0 = (size_t)blockIdx.x * 64;
    __half* hb = g_h2h + (size_t)t * 64 * NB + nb0;
#pragma unroll
    for (int k = 0; k < 4; k++) {
        int co = g * 8 + 2 * k;
        float2 u = unp(accA[k]);
        float2 v = unp(accB[k]);
        hb[(size_t)co * NB + r2]            = __float2half_rn(fmaxf(u.x, 0.f));
        hb[(size_t)(co + 1) * NB + r2]      = __float2half_rn(fmaxf(u.y, 0.f));
        hb[(size_t)co * NB + r2 + 32]       = __float2half_rn(fmaxf(v.x, 0.f));
        hb[(size_t)(co + 1) * NB + r2 + 32] = __float2half_rn(fmaxf(v.y, 0.f));
    }
}

/* ---------------- F2: temporal convs (needed taps) + head, packed --------- */
#define F2_SMEM ((5 * 4096 + 192) * 4)
__global__ __launch_bounds__(128) void k_f2(const float* __restrict__ tc1w,
                                            const float* __restrict__ tc1b,
                                            const float* __restrict__ tc2w,
                                            const float* __restrict__ tc2b,
                                            const float* __restrict__ ow,
                                            const float* __restrict__ ob,
                                            float* __restrict__ out) {
    extern __shared__ __align__(16) float sm[];
    float* w10 = sm;            /* [ci][co] = tc1_w[co][ci][tap] */
    float* w11 = sm + 4096;
    float* w12 = sm + 8192;
    float* w20 = sm + 12288;    /* [co2][ci] = tc2_w[co2][ci][tap] */
    float* w21 = sm + 16384;
    float* tb1 = sm + 20480;
    float* tb2 = tb1 + 64;
    float* ows = tb2 + 64;
    int tid = threadIdx.x;
    for (int i = tid; i < 4096; i += 128) {
        int ci = i >> 6, co = i & 63;
        int s1 = (co * 64 + ci) * 3;
        w10[i] = tc1w[s1];
        w11[i] = tc1w[s1 + 1];
        w12[i] = tc1w[s1 + 2];
        w20[i] = tc2w[i * 3];
        w21[i] = tc2w[i * 3 + 1];
    }
    if (tid < 64) { tb1[tid] = tc1b[tid]; tb2[tid] = tc2b[tid]; ows[tid] = ow[tid]; }
    __syncthreads();
    int idx = blockIdx.x * 128 + tid;   /* b fastest: coalesced h2 reads */
    if (idx >= NB) return;
    int b = idx & 7, n = idx >> 3;

    ull a10[32], a11[32];
    const ull* tb1p = (const ull*)tb1;
#pragma unroll
    for (int p = 0; p < 32; p++) { a10[p] = tb1p[p]; a11[p] = tb1p[p]; }

    const __half* hp = g_h2h + idx;     /* + (t*64+ci)*NB */
    float s9  = __half2float(hp[0]);
    float s10 = __half2float(hp[(size_t)64 * NB]);
    float s11 = __half2float(hp[(size_t)128 * NB]);
    for (int ci = 0; ci < 64; ci++) {
        float n9 = 0.f, n10 = 0.f, n11 = 0.f;
        if (ci < 63) {   /* prefetch next plane */
            n9  = __half2float(hp[(size_t)(ci + 1) * NB]);
            n10 = __half2float(hp[(size_t)(64 + ci + 1) * NB]);
            n11 = __half2float(hp[(size_t)(128 + ci + 1) * NB]);
        }
        ull b9 = bc2(s9), b10 = bc2(s10), b11 = bc2(s11);
        const ulonglong2* p0 = (const ulonglong2*)(w10 + ci * 64);
        const ulonglong2* p1 = (const ulonglong2*)(w11 + ci * 64);
        const ulonglong2* p2 = (const ulonglong2*)(w12 + ci * 64);
#pragma unroll
        for (int q = 0; q < 16; q++) {
            ulonglong2 t0 = p0[q], t1 = p1[q], t2 = p2[q];
            a10[2 * q]     = fma2(b9,  t0.x, a10[2 * q]);
            a10[2 * q]     = fma2(b10, t1.x, a10[2 * q]);
            a10[2 * q]     = fma2(b11, t2.x, a10[2 * q]);
            a10[2 * q + 1] = fma2(b9,  t0.y, a10[2 * q + 1]);
            a10[2 * q + 1] = fma2(b10, t1.y, a10[2 * q + 1]);
            a10[2 * q + 1] = fma2(b11, t2.y, a10[2 * q + 1]);
            a11[2 * q]     = fma2(b10, t0.x, a11[2 * q]);
            a11[2 * q]     = fma2(b11, t1.x, a11[2 * q]);
            a11[2 * q + 1] = fma2(b10, t0.y, a11[2 * q + 1]);
            a11[2 * q + 1] = fma2(b11, t1.y, a11[2 * q + 1]);
        }
        s9 = n9; s10 = n10; s11 = n11;
    }
#pragma unroll
    for (int p = 0; p < 32; p++) {
        float2 u = unp(a10[p]);
        a10[p] = pk2(fmaxf(u.x, 0.f), fmaxf(u.y, 0.f));
        float2 v = unp(a11[p]);
        a11[p] = pk2(fmaxf(v.x, 0.f), fmaxf(v.y, 0.f));
    }

    float acc = 0.f;
    for (int co = 0; co < 64; co++) {
        ull sp0 = 0, sp1 = 0, sp2 = 0, sp3 = 0;
        const ulonglong2* pa = (const ulonglong2*)(w20 + co * 64);
        const ulonglong2* pb = (const ulonglong2*)(w21 + co * 64);
#pragma unroll
        for (int q = 0; q < 16; q++) {
            ulonglong2 wa = pa[q], wb = pb[q];
            sp0 = fma2(a10[2 * q],     wa.x, sp0);
            sp1 = fma2(a10[2 * q + 1], wa.y, sp1);
            sp2 = fma2(a11[2 * q],     wb.x, sp2);
            sp3 = fma2(a11[2 * q + 1], wb.y, sp3);
        }
        float2 u0 = unp(sp0), u1 = unp(sp1), u2 = unp(sp2), u3 = unp(sp3);
        float s = tb2[co] + ((u0.x + u0.y) + (u1.x + u1.y))
                          + ((u2.x + u2.y) + (u3.x + u3.y));
        acc = fmaf(fmaxf(s, 0.f), ows[co], acc);
    }
    out[b * NN + n] = acc + ob[0];
}

/* ---------------- launch ---------------- */
extern "C" void kernel_launch(void* const* d_in, const int* in_sizes, int n_in,
                              void* d_out, int out_size) {
    const float* X    = (const float*)d_in[0];
    const int*   ei   = (const int*)d_in[1];
    const float* ew   = (const float*)d_in[2];
    const float* W1   = (const float*)d_in[3];
    const float* b1   = (const float*)d_in[4];
    const float* W2   = (const float*)d_in[5];
    const float* b2   = (const float*)d_in[6];
    const float* tc1w = (const float*)d_in[7];
    const float* tc1b = (const float*)d_in[8];
    const float* tc2w = (const float*)d_in[9];
    const float* tc2b = (const float*)d_in[10];
    const float* ow   = (const float*)d_in[11];
    const float* ob   = (const float*)d_in[12];
    float* out = (float*)d_out;

    cudaFuncSetAttribute(k_f2, cudaFuncAttributeMaxDynamicSharedMemorySize, F2_SMEM);

    k_zero<<<(NN + 255) / 256, 256>>>();
    k_deg<<<(EE + 255) / 256, 256>>>(ei, ew);
    k_dinv<<<(NN + 255) / 256, 256>>>();
    k_fill<<<(EE + 255) / 256, 256>>>(ei, ew);
    k_aggAH1<<<(ROWS + 255) / 256, 256>>>(X, W1, b1);
    dim3 gC(NN / 8, TS);
    k_aggCF1<<<gC, 256>>>(W2, b2);
    k_f2<<<(NB + 127) / 128, 128, F2_SMEM>>>(tc1w, tc1b, tc2w, tc2b, ow, ob, out);
}

// round 7
// speedup vs baseline: 2.2677x; 1.3513x over previous
#include <cuda_runtime.h>
#include <cuda_fp16.h>

#define NN 10000
#define EE 160000
#define BB 8
#define TT 12
#define HH 64
#define TS 3
#define T0 9
#define ROWS (TS*NN*BB)   /* 240000 rows of 64 features */
#define NB  (BB*NN)       /* 80000 (n,b) rows */
#define KD  192           /* stage1 K = 3t * 64ci */
#define P1  200           /* smem pitch (halves) for K=192 tiles: (P/2)%32==4 */
#define P2  136           /* smem pitch for K=128 tiles: 68%32==4 */

typedef unsigned long long ull;
typedef unsigned int uint;

/* ---------------- device scratch (no allocs allowed) ---------------- */
__device__ float  g_deg[NN];
__device__ float  g_self[NN];
__device__ float  g_dinv[NN];
__device__ int    g_cnt[NN];
__device__ int    g_off[NN];
__device__ int    g_end[NN];
__device__ int    g_alloc;
__device__ ull    g_csr[EE];            /* packed (src low, w high) */
__device__ uint4  g_h1h[TS * NN * 64];  /* fp16 h1: [t][n][b][64]  30.7MB */
__device__ __half g_h2h[(size_t)NB * KD];  /* fp16 h2: [nb][t*64+ci] 30.7MB */
__device__ __half g_B1h[128 * P1];      /* stage1 weights B^T padded */
__device__ __half g_B2h[64 * P2];       /* stage2 weights B^T padded */

/* ---------------- packed f32x2 helpers ---------------- */
__device__ __forceinline__ ull fma2(ull a, ull b, ull c) {
    ull d;
    asm("fma.rn.f32x2 %0, %1, %2, %3;" : "=l"(d) : "l"(a), "l"(b), "l"(c));
    return d;
}
__device__ __forceinline__ ull bc2(float s) {
    ull r;
    asm("mov.b64 %0, {%1, %1};" : "=l"(r) : "r"(__float_as_uint(s)));
    return r;
}
__device__ __forceinline__ float2 unp(ull v) {
    unsigned lo, hi;
    asm("mov.b64 {%0, %1}, %2;" : "=r"(lo), "=r"(hi) : "l"(v));
    return make_float2(__uint_as_float(lo), __uint_as_float(hi));
}
__device__ __forceinline__ ull pk2(float a, float b) {
    ull r;
    asm("mov.b64 %0, {%1, %2};" : "=l"(r) : "r"(__float_as_uint(a)), "r"(__float_as_uint(b)));
    return r;
}
/* mma.sync m16n8k16 row.col f32.f16.f16.f32, accumulate in place */
__device__ __forceinline__ void mma16816(float& c0, float& c1, float& c2, float& c3,
                                         uint a0, uint a1, uint a2, uint a3,
                                         uint b0, uint b1) {
    asm volatile("mma.sync.aligned.m16n8k16.row.col.f32.f16.f16.f32 "
                 "{%0,%1,%2,%3}, {%4,%5,%6,%7}, {%8,%9}, {%0,%1,%2,%3};"
                 : "+f"(c0), "+f"(c1), "+f"(c2), "+f"(c3)
                 : "r"(a0), "r"(a1), "r"(a2), "r"(a3), "r"(b0), "r"(b1));
}

/* ---------------- graph preprocessing ---------------- */
__global__ void k_zero() {
    int i = blockIdx.x * blockDim.x + threadIdx.x;
    if (i < NN) { g_deg[i] = 0.f; g_cnt[i] = 0; }
    if (i == 0) g_alloc = 0;
}

__global__ void k_deg(const int* __restrict__ ei, const float* __restrict__ w) {
    int e = blockIdx.x * blockDim.x + threadIdx.x;
    if (e >= EE) return;
    int d = ei[EE + e];
    float wv = w[e];
    atomicAdd(&g_deg[d], wv);
    atomicAdd(&g_cnt[d], 1);
}

__global__ void k_dinv() {
    int i = blockIdx.x * blockDim.x + threadIdx.x;
    int lane = threadIdx.x & 31;
    int valid = (i < NN);
    int c = valid ? g_cnt[i] : 0;
    int incl = c;
#pragma unroll
    for (int d = 1; d < 32; d <<= 1) {
        int v = __shfl_up_sync(0xffffffffu, incl, d);
        if (lane >= d) incl += v;
    }
    int wtot = __shfl_sync(0xffffffffu, incl, 31);
    int base = 0;
    if (lane == 31 && wtot > 0) base = atomicAdd(&g_alloc, wtot);
    base = __shfl_sync(0xffffffffu, base, 31);
    if (!valid) return;
    int off = base + incl - c;
    g_off[i] = off;
    g_end[i] = off + c;
    g_cnt[i] = off;
    float dv = rsqrtf(g_deg[i] + 1.0f);
    g_dinv[i] = dv;
    g_self[i] = dv * dv;
}

__global__ void k_fill(const int* __restrict__ ei, const float* __restrict__ w) {
    int e = blockIdx.x * blockDim.x + threadIdx.x;
    if (e >= EE) return;
    int s = ei[e], d = ei[EE + e];
    float wv = w[e];
    float nr = g_dinv[s] * wv * g_dinv[d];
    int p = atomicAdd(&g_cnt[d], 1);
    g_csr[p] = ((ull)__float_as_uint(nr) << 32) | (uint)s;
}

/* ------- prep conv weights as fp16 B^T (padded) for the mma kernel -------- */
/* B1^T[j][k]: j = ot*64 + co (ot 0 -> out t=10, 1 -> out t=11), k = t*64+ci  */
/*   ot=0: tap = t; ot=1: tap = t-1 (t>=1) else 0                              */
/* B2^T[co2][k]: k = ot*64 + co: ot=0 -> tc2w tap0, ot=1 -> tap1               */
__global__ void k_prepW(const float* __restrict__ tc1w,
                        const float* __restrict__ tc2w) {
    int tid = blockIdx.x * blockDim.x + threadIdx.x;
    for (int i = tid; i < 128 * P1; i += 1024 * 32) {} /* noop guard */
    for (int i = tid; i < 128 * P1; i += gridDim.x * blockDim.x) {
        int j = i / P1, k = i % P1;
        float v = 0.f;
        if (k < KD) {
            int t = k >> 6, ci = k & 63;
            int ot = j >> 6, co = j & 63;
            if (ot == 0) v = tc1w[(co * 64 + ci) * 3 + t];
            else if (t >= 1) v = tc1w[(co * 64 + ci) * 3 + (t - 1)];
        }
        g_B1h[i] = __float2half_rn(v);
    }
    for (int i = tid; i < 64 * P2; i += gridDim.x * blockDim.x) {
        int j = i / P2, k = i % P2;
        float v = 0.f;
        if (k < 128) {
            int ot = k >> 6, co = k & 63;
            v = tc2w[(j * 64 + co) * 3 + ot];
        }
        g_B2h[i] = __float2half_rn(v);
    }
}

/* ------- fused stage A: 2-wide agg of X + h1 = relu(A@W1+b1) -> fp16 ------ */
__global__ __launch_bounds__(256) void k_aggAH1(const float* __restrict__ X,
                                                const float* __restrict__ W1,
                                                const float* __restrict__ b1) {
    __shared__ __align__(16) float sW1[128];
    __shared__ __align__(16) float sb1[64];
    int tid = threadIdx.x;
    if (tid < 128) sW1[tid] = W1[tid];
    if (tid < 64)  sb1[tid] = b1[tid];
    __syncthreads();

    int idx = blockIdx.x * 256 + tid;
    if (idx >= ROWS) return;
    int b = idx & 7;
    int nt = idx >> 3;
    int n = nt % NN;
    int t = nt / NN;
    const float2* base = (const float2*)X + (size_t)(b * TT + T0 + t) * NN;
    float2 x = base[n];
    float sf = g_self[n];
    float ax = sf * x.x, ay = sf * x.y;
    int j = g_off[n], j1 = g_end[n];
    for (; j + 2 <= j1; j += 2) {
        ull e0 = g_csr[j], e1 = g_csr[j + 1];
        int s0 = (int)(e0 & 0xffffffffu);
        int s1 = (int)(e1 & 0xffffffffu);
        float2 xs0 = base[s0];
        float2 xs1 = base[s1];
        float nr0 = __uint_as_float((uint)(e0 >> 32));
        float nr1 = __uint_as_float((uint)(e1 >> 32));
        ax = fmaf(nr0, xs0.x, ax);
        ay = fmaf(nr0, xs0.y, ay);
        ax = fmaf(nr1, xs1.x, ax);
        ay = fmaf(nr1, xs1.y, ay);
    }
    if (j < j1) {
        ull e = g_csr[j];
        int s = (int)(e & 0xffffffffu);
        float nr = __uint_as_float((uint)(e >> 32));
        float2 xs = base[s];
        ax = fmaf(nr, xs.x, ax);
        ay = fmaf(nr, xs.y, ay);
    }
    const float4* w0 = (const float4*)sW1;
    const float4* w1 = (const float4*)(sW1 + 64);
    const float4* bb = (const float4*)sb1;
    uint4* dst = g_h1h + (size_t)idx * 8;
#pragma unroll
    for (int q8 = 0; q8 < 8; q8++) {
        uint4 o;
        uint* op = (uint*)&o;
#pragma unroll
        for (int h = 0; h < 4; h++) {
            int q = q8 * 2 + (h >> 1);
            float4 W0 = w0[q], W1v = w1[q], Bv = bb[q];
            float v0, v1;
            if ((h & 1) == 0) {
                v0 = fmaxf(fmaf(ax, W0.x, fmaf(ay, W1v.x, Bv.x)), 0.f);
                v1 = fmaxf(fmaf(ax, W0.y, fmaf(ay, W1v.y, Bv.y)), 0.f);
            } else {
                v0 = fmaxf(fmaf(ax, W0.z, fmaf(ay, W1v.z, Bv.z)), 0.f);
                v1 = fmaxf(fmaf(ax, W0.w, fmaf(ay, W1v.w, Bv.w)), 0.f);
            }
            __half2 hh = __floats2half2_rn(v0, v1);
            op[h] = *(uint*)&hh;
        }
        dst[q8] = o;
    }
}

/* ------- fused: 64-wide fp16 gather agg + h2 = relu(C@W2+b2) -> fp16 ------ */
__device__ __forceinline__ void acc_row(const uint4* h1t, int s, int lane,
                                        float nr, float* aA, float* aB) {
    const uint4* rs = h1t + (size_t)s * 64 + lane;
    uint4 v0 = rs[0], v1 = rs[32];
    const __half2* p0 = (const __half2*)&v0;
    const __half2* p1 = (const __half2*)&v1;
#pragma unroll
    for (int k = 0; k < 4; k++) {
        float2 f0 = __half22float2(p0[k]);
        float2 f1 = __half22float2(p1[k]);
        aA[2 * k]     = fmaf(nr, f0.x, aA[2 * k]);
        aA[2 * k + 1] = fmaf(nr, f0.y, aA[2 * k + 1]);
        aB[2 * k]     = fmaf(nr, f1.x, aB[2 * k]);
        aB[2 * k + 1] = fmaf(nr, f1.y, aB[2 * k + 1]);
    }
}

__global__ __launch_bounds__(256) void k_aggCF1(const float* __restrict__ W2,
                                                const float* __restrict__ b2) {
    __shared__ float sC[64 * 65];
    __shared__ __align__(16) float sW2[4096];
    int tid = threadIdx.x;
    int t = blockIdx.y;
    for (int i = tid; i < 1024; i += 256)
        ((float4*)sW2)[i] = ((const float4*)W2)[i];

    int warp = tid >> 5, lane = tid & 31;
    int wi = blockIdx.x * 8 + warp;

    const uint4* h1t = g_h1h + (size_t)t * NN * 64;
    const uint4* rn = h1t + (size_t)wi * 64 + lane;
    float sf = g_self[wi];
    float aA[8], aB[8];
    {
        uint4 v0 = rn[0], v1 = rn[32];
        const __half2* p0 = (const __half2*)&v0;
        const __half2* p1 = (const __half2*)&v1;
#pragma unroll
        for (int k = 0; k < 4; k++) {
            float2 f0 = __half22float2(p0[k]);
            float2 f1 = __half22float2(p1[k]);
            aA[2 * k]     = sf * f0.x;
            aA[2 * k + 1] = sf * f0.y;
            aB[2 * k]     = sf * f1.x;
            aB[2 * k + 1] = sf * f1.y;
        }
    }
    int j = g_off[wi], j1 = g_end[wi];
    for (; j + 2 <= j1; j += 2) {
        ull e0 = g_csr[j], e1 = g_csr[j + 1];
        int s0 = (int)(e0 & 0xffffffffu);
        int s1 = (int)(e1 & 0xffffffffu);
        float nr0 = __uint_as_float((uint)(e0 >> 32));
        float nr1 = __uint_as_float((uint)(e1 >> 32));
        const uint4* rs0 = h1t + (size_t)s0 * 64 + lane;
        const uint4* rs1 = h1t + (size_t)s1 * 64 + lane;
        uint4 a0 = rs0[0], a1 = rs0[32];
        uint4 b0 = rs1[0], b1 = rs1[32];
        {
            const __half2* p0 = (const __half2*)&a0;
            const __half2* p1 = (const __half2*)&a1;
            const __half2* q0 = (const __half2*)&b0;
            const __half2* q1 = (const __half2*)&b1;
#pragma unroll
            for (int k = 0; k < 4; k++) {
                float2 f0 = __half22float2(p0[k]);
                float2 f1 = __half22float2(p1[k]);
                float2 g0 = __half22float2(q0[k]);
                float2 g1 = __half22float2(q1[k]);
                aA[2 * k]     = fmaf(nr0, f0.x, aA[2 * k]);
                aA[2 * k + 1] = fmaf(nr0, f0.y, aA[2 * k + 1]);
                aB[2 * k]     = fmaf(nr0, f1.x, aB[2 * k]);
                aB[2 * k + 1] = fmaf(nr0, f1.y, aB[2 * k + 1]);
                aA[2 * k]     = fmaf(nr1, g0.x, aA[2 * k]);
                aA[2 * k + 1] = fmaf(nr1, g0.y, aA[2 * k + 1]);
                aB[2 * k]     = fmaf(nr1, g1.x, aB[2 * k]);
                aB[2 * k + 1] = fmaf(nr1, g1.y, aB[2 * k + 1]);
            }
        }
    }
    if (j < j1) {
        ull e = g_csr[j];
        int s = (int)(e & 0xffffffffu);
        float nr = __uint_as_float((uint)(e >> 32));
        acc_row(h1t, s, lane, nr, aA, aB);
    }
    {
        int bl = lane >> 3;
        int f0 = (lane & 7) * 8;
        float* pA = sC + (warp * 8 + bl) * 65 + f0;
        float* pB = sC + (warp * 8 + 4 + bl) * 65 + f0;
#pragma unroll
        for (int k = 0; k < 8; k++) { pA[k] = aA[k]; pB[k] = aB[k]; }
    }
    __syncthreads();

    int r2 = tid & 31, g = tid >> 5;
    ull accA[4], accB[4];
#pragma unroll
    for (int k = 0; k < 4; k++) {
        float2 bbv = __ldg((const float2*)b2 + g * 4 + k);
        accA[k] = pk2(bbv.x, bbv.y);
        accB[k] = accA[k];
    }
    const float* cA = sC + r2 * 65;
    const float* cB = sC + (r2 + 32) * 65;
#pragma unroll 4
    for (int ci = 0; ci < 64; ci++) {
        ull xA = bc2(cA[ci]);
        ull xB = bc2(cB[ci]);
        const ulonglong2* wp = (const ulonglong2*)(sW2 + ci * 64 + g * 8);
        ulonglong2 wa = wp[0], wb = wp[1];
        accA[0] = fma2(xA, wa.x, accA[0]);
        accA[1] = fma2(xA, wa.y, accA[1]);
        accA[2] = fma2(xA, wb.x, accA[2]);
        accA[3] = fma2(xA, wb.y, accA[3]);
        accB[0] = fma2(xB, wa.x, accB[0]);
        accB[1] = fma2(xB, wa.y, accB[1]);
        accB[2] = fma2(xB, wb.x, accB[2]);
        accB[3] = fma2(xB, wb.y, accB[3]);
    }
    /* store fp16 to [nb][t*64+co], half2 per co pair */
    int nbA = blockIdx.x * 64 + r2;
    int nbB = nbA + 32;
    __half* rowA = g_h2h + (size_t)nbA * KD + t * 64;
    __half* rowB = g_h2h + (size_t)nbB * KD + t * 64;
#pragma unroll
    for (int k = 0; k < 4; k++) {
        int co = g * 8 + 2 * k;
        float2 u = unp(accA[k]);
        float2 v = unp(accB[k]);
        *(__half2*)(rowA + co) = __floats2half2_rn(fmaxf(u.x, 0.f), fmaxf(u.y, 0.f));
        *(__half2*)(rowB + co) = __floats2half2_rn(fmaxf(v.x, 0.f), fmaxf(v.y, 0.f));
    }
}

/* ---------------- F2: tensor-core temporal convs + head ------------------- */
/* smem: A_s 128xP1, B1t 128xP1, A2 128xP2, B2t 64xP2, biases + ow           */
#define F2_SMEM (128*P1*2 + 128*P1*2 + 128*P2*2 + 64*P2*2 + (128+64+64)*4)
__global__ __launch_bounds__(256, 1) void k_f2(const float* __restrict__ tc1b,
                                               const float* __restrict__ tc2b,
                                               const float* __restrict__ ow,
                                               const float* __restrict__ ob,
                                               float* __restrict__ out) {
    extern __shared__ __align__(16) char smraw[];
    __half* A_s  = (__half*)smraw;                       /* [128][P1] */
    __half* B1t  = A_s + 128 * P1;                       /* [128][P1] */
    __half* A2   = B1t + 128 * P1;                       /* [128][P2] */
    __half* B2t  = A2 + 128 * P2;                        /* [64][P2]  */
    float*  sb1f = (float*)(B2t + 64 * P2);              /* [128] */
    float*  sb2f = sb1f + 128;                           /* [64] */
    float*  ows  = sb2f + 64;                            /* [64] */

    int tid = threadIdx.x;
    int blk = blockIdx.x;

    /* load A tile: 128 rows x 192 halves (24 uint4/row), coalesced */
    {
        const uint4* src = (const uint4*)(g_h2h + (size_t)blk * 128 * KD);
        for (int i = tid; i < 128 * 24; i += 256) {
            int r = i / 24, c = i % 24;
            ((uint4*)(A_s + r * P1))[c] = src[i];
        }
    }
    /* load padded weights straight */
    {
        const uint4* s1 = (const uint4*)g_B1h;
        uint4* d1 = (uint4*)B1t;
        for (int i = tid; i < 128 * P1 / 8; i += 256) d1[i] = s1[i];
        const uint4* s2 = (const uint4*)g_B2h;
        uint4* d2 = (uint4*)B2t;
        for (int i = tid; i < 64 * P2 / 8; i += 256) d2[i] = s2[i];
    }
    if (tid < 128) sb1f[tid] = tc1b[tid & 63];
    else if (tid < 192) sb2f[tid - 128] = tc2b[tid - 128];
    else if (tid < 256) ows[tid - 192] = ow[tid - 192];
    __syncthreads();

    int warp = tid >> 5, lane = tid & 31;
    int g = lane >> 2, tc = lane & 3;
    int m0 = warp * 16;
    int rA = (m0 + g) * P1, rA8 = (m0 + g + 8) * P1;

    /* ---- stage 1: [16 x 192] x [192 x 128] per warp ---- */
    float c1[16][4];
#pragma unroll
    for (int nt = 0; nt < 16; nt++) {
        float bb0 = sb1f[nt * 8 + 2 * tc];
        float bb1 = sb1f[nt * 8 + 2 * tc + 1];
        c1[nt][0] = bb0; c1[nt][1] = bb1; c1[nt][2] = bb0; c1[nt][3] = bb1;
    }
#pragma unroll
    for (int k0 = 0; k0 < 12; k0++) {
        int kc = k0 * 16 + 2 * tc;
        uint a0 = *(const uint*)(A_s + rA + kc);
        uint a1 = *(const uint*)(A_s + rA8 + kc);
        uint a2 = *(const uint*)(A_s + rA + kc + 8);
        uint a3 = *(const uint*)(A_s + rA8 + kc + 8);
#pragma unroll
        for (int nt = 0; nt < 16; nt++) {
            const __half* bp = B1t + (nt * 8 + g) * P1 + kc;
            uint b0 = *(const uint*)bp;
            uint b1 = *(const uint*)(bp + 8);
            mma16816(c1[nt][0], c1[nt][1], c1[nt][2], c1[nt][3],
                     a0, a1, a2, a3, b0, b1);
        }
    }
    /* relu -> fp16 -> A2 (own rows only) */
    {
        __half* w0 = A2 + (m0 + g) * P2;
        __half* w8 = A2 + (m0 + g + 8) * P2;
#pragma unroll
        for (int nt = 0; nt < 16; nt++) {
            int col = nt * 8 + 2 * tc;
            *(__half2*)(w0 + col) = __floats2half2_rn(fmaxf(c1[nt][0], 0.f),
                                                      fmaxf(c1[nt][1], 0.f));
            *(__half2*)(w8 + col) = __floats2half2_rn(fmaxf(c1[nt][2], 0.f),
                                                      fmaxf(c1[nt][3], 0.f));
        }
    }
    __syncwarp();

    /* ---- stage 2: [16 x 128] x [128 x 64] per warp ---- */
    float c2[8][4];
#pragma unroll
    for (int nt = 0; nt < 8; nt++) {
        float bb0 = sb2f[nt * 8 + 2 * tc];
        float bb1 = sb2f[nt * 8 + 2 * tc + 1];
        c2[nt][0] = bb0; c2[nt][1] = bb1; c2[nt][2] = bb0; c2[nt][3] = bb1;
    }
    int r2A = (m0 + g) * P2, r2A8 = (m0 + g + 8) * P2;
#pragma unroll
    for (int k0 = 0; k0 < 8; k0++) {
        int kc = k0 * 16 + 2 * tc;
        uint a0 = *(const uint*)(A2 + r2A + kc);
        uint a1 = *(const uint*)(A2 + r2A8 + kc);
        uint a2 = *(const uint*)(A2 + r2A + kc + 8);
        uint a3 = *(const uint*)(A2 + r2A8 + kc + 8);
#pragma unroll
        for (int nt = 0; nt < 8; nt++) {
            const __half* bp = B2t + (nt * 8 + g) * P2 + kc;
            uint b0 = *(const uint*)bp;
            uint b1 = *(const uint*)(bp + 8);
            mma16816(c2[nt][0], c2[nt][1], c2[nt][2], c2[nt][3],
                     a0, a1, a2, a3, b0, b1);
        }
    }
    /* ---- head: relu(t2) . ow, reduce over tc quad ---- */
    float accR = 0.f, accR8 = 0.f;
#pragma unroll
    for (int nt = 0; nt < 8; nt++) {
        int col = nt * 8 + 2 * tc;
        float w0 = ows[col], w1 = ows[col + 1];
        accR  = fmaf(fmaxf(c2[nt][0], 0.f), w0, accR);
        accR  = fmaf(fmaxf(c2[nt][1], 0.f), w1, accR);
        accR8 = fmaf(fmaxf(c2[nt][2], 0.f), w0, accR8);
        accR8 = fmaf(fmaxf(c2[nt][3], 0.f), w1, accR8);
    }
    accR  += __shfl_xor_sync(0xffffffffu, accR, 1);
    accR  += __shfl_xor_sync(0xffffffffu, accR, 2);
    accR8 += __shfl_xor_sync(0xffffffffu, accR8, 1);
    accR8 += __shfl_xor_sync(0xffffffffu, accR8, 2);
    if (tc == 0) {
        float ob0 = __ldg(ob);
        int nb1 = blk * 128 + m0 + g;
        int nb2 = nb1 + 8;
        out[(nb1 & 7) * NN + (nb1 >> 3)] = accR + ob0;
        out[(nb2 & 7) * NN + (nb2 >> 3)] = accR8 + ob0;
    }
}

/* ---------------- launch ---------------- */
extern "C" void kernel_launch(void* const* d_in, const int* in_sizes, int n_in,
                              void* d_out, int out_size) {
    const float* X    = (const float*)d_in[0];
    const int*   ei   = (const int*)d_in[1];
    const float* ew   = (const float*)d_in[2];
    const float* W1   = (const float*)d_in[3];
    const float* b1   = (const float*)d_in[4];
    const float* W2   = (const float*)d_in[5];
    const float* b2   = (const float*)d_in[6];
    const float* tc1w = (const float*)d_in[7];
    const float* tc1b = (const float*)d_in[8];
    const float* tc2w = (const float*)d_in[9];
    const float* tc2b = (const float*)d_in[10];
    const float* ow   = (const float*)d_in[11];
    const float* ob   = (const float*)d_in[12];
    float* out = (float*)d_out;

    cudaFuncSetAttribute(k_f2, cudaFuncAttributeMaxDynamicSharedMemorySize, F2_SMEM);

    k_prepW<<<32, 256>>>(tc1w, tc2w);
    k_zero<<<(NN + 255) / 256, 256>>>();
    k_deg<<<(EE + 255) / 256, 256>>>(ei, ew);
    k_dinv<<<(NN + 255) / 256, 256>>>();
    k_fill<<<(EE + 255) / 256, 256>>>(ei, ew);
    k_aggAH1<<<(ROWS + 255) / 256, 256>>>(X, W1, b1);
    dim3 gC(NN / 8, TS);
    k_aggCF1<<<gC, 256>>>(W2, b2);
    k_f2<<<NB / 128, 256, F2_SMEM>>>(tc1b, tc2b, ow, ob, out);
}

// round 8
// speedup vs baseline: 2.6814x; 1.1825x over previous
#include <cuda_runtime.h>
#include <cuda_fp16.h>

#define NN 10000
#define EE 160000
#define BB 8
#define TT 12
#define HH 64
#define TS 3
#define T0 9
#define ROWS (TS*NN*BB)   /* 240000 rows of 64 features */
#define NB  (BB*NN)       /* 80000 (n,b) rows */
#define KD  192           /* stage1 K = 3t * 64ci */
#define P1  200           /* smem pitch (halves) for K=192 tiles */
#define P2  136           /* smem pitch for K=128 tiles */

typedef unsigned long long ull;
typedef unsigned int uint;

/* ---------------- device scratch (no allocs allowed) ---------------- */
__device__ float  g_deg[NN];
__device__ float  g_self[NN];
__device__ float  g_dinv[NN];
__device__ int    g_cnt[NN];
__device__ int    g_off[NN];
__device__ int    g_end[NN];
__device__ int    g_alloc;
__device__ ull    g_csr[EE];            /* packed (src low, w high) */
__device__ uint4  g_h1h[TS * NN * 64];  /* fp16 h1: [t][n][b][64]  30.7MB */
__device__ __half g_h2h[(size_t)NB * KD];  /* fp16 h2: [nb][t*64+ci] 30.7MB */
__device__ __half g_B1h[128 * P1];      /* stage1 weights B^T padded */
__device__ __half g_B2h[64 * P2];       /* stage2 weights B^T padded */

/* ---------------- packed f32x2 helpers ---------------- */
__device__ __forceinline__ ull fma2(ull a, ull b, ull c) {
    ull d;
    asm("fma.rn.f32x2 %0, %1, %2, %3;" : "=l"(d) : "l"(a), "l"(b), "l"(c));
    return d;
}
__device__ __forceinline__ ull bc2(float s) {
    ull r;
    asm("mov.b64 %0, {%1, %1};" : "=l"(r) : "r"(__float_as_uint(s)));
    return r;
}
__device__ __forceinline__ float2 unp(ull v) {
    unsigned lo, hi;
    asm("mov.b64 {%0, %1}, %2;" : "=r"(lo), "=r"(hi) : "l"(v));
    return make_float2(__uint_as_float(lo), __uint_as_float(hi));
}
__device__ __forceinline__ ull pk2(float a, float b) {
    ull r;
    asm("mov.b64 %0, {%1, %2};" : "=l"(r) : "r"(__float_as_uint(a)), "r"(__float_as_uint(b)));
    return r;
}
/* mma.sync m16n8k16 row.col f32.f16.f16.f32, accumulate in place */
__device__ __forceinline__ void mma16816(float& c0, float& c1, float& c2, float& c3,
                                         uint a0, uint a1, uint a2, uint a3,
                                         uint b0, uint b1) {
    asm volatile("mma.sync.aligned.m16n8k16.row.col.f32.f16.f16.f32 "
                 "{%0,%1,%2,%3}, {%4,%5,%6,%7}, {%8,%9}, {%0,%1,%2,%3};"
                 : "+f"(c0), "+f"(c1), "+f"(c2), "+f"(c3)
                 : "r"(a0), "r"(a1), "r"(a2), "r"(a3), "r"(b0), "r"(b1));
}

/* ------- prep: zero state + build fp16 conv-weight matrices --------------- */
__global__ void k_prepW(const float* __restrict__ tc1w,
                        const float* __restrict__ tc2w) {
    int tid = blockIdx.x * blockDim.x + threadIdx.x;
    int stride = gridDim.x * blockDim.x;
    if (tid == 0) g_alloc = 0;
    for (int i = tid; i < NN; i += stride) { g_deg[i] = 0.f; g_cnt[i] = 0; }
    for (int i = tid; i < 128 * P1; i += stride) {
        int j = i / P1, k = i % P1;
        float v = 0.f;
        if (k < KD) {
            int t = k >> 6, ci = k & 63;
            int ot = j >> 6, co = j & 63;
            if (ot == 0) v = tc1w[(co * 64 + ci) * 3 + t];
            else if (t >= 1) v = tc1w[(co * 64 + ci) * 3 + (t - 1)];
        }
        g_B1h[i] = __float2half_rn(v);
    }
    for (int i = tid; i < 64 * P2; i += stride) {
        int j = i / P2, k = i % P2;
        float v = 0.f;
        if (k < 128) {
            int ot = k >> 6, co = k & 63;
            v = tc2w[(j * 64 + co) * 3 + ot];
        }
        g_B2h[i] = __float2half_rn(v);
    }
}

__global__ void k_deg(const int* __restrict__ ei, const float* __restrict__ w) {
    int e = blockIdx.x * blockDim.x + threadIdx.x;
    if (e >= EE) return;
    int d = ei[EE + e];
    float wv = w[e];
    atomicAdd(&g_deg[d], wv);
    atomicAdd(&g_cnt[d], 1);
}

__global__ void k_dinv() {
    int i = blockIdx.x * blockDim.x + threadIdx.x;
    int lane = threadIdx.x & 31;
    int valid = (i < NN);
    int c = valid ? g_cnt[i] : 0;
    int incl = c;
#pragma unroll
    for (int d = 1; d < 32; d <<= 1) {
        int v = __shfl_up_sync(0xffffffffu, incl, d);
        if (lane >= d) incl += v;
    }
    int wtot = __shfl_sync(0xffffffffu, incl, 31);
    int base = 0;
    if (lane == 31 && wtot > 0) base = atomicAdd(&g_alloc, wtot);
    base = __shfl_sync(0xffffffffu, base, 31);
    if (!valid) return;
    int off = base + incl - c;
    g_off[i] = off;
    g_end[i] = off + c;
    g_cnt[i] = off;
    float dv = rsqrtf(g_deg[i] + 1.0f);
    g_dinv[i] = dv;
    g_self[i] = dv * dv;
}

__global__ void k_fill(const int* __restrict__ ei, const float* __restrict__ w) {
    int e = blockIdx.x * blockDim.x + threadIdx.x;
    if (e >= EE) return;
    int s = ei[e], d = ei[EE + e];
    float wv = w[e];
    float nr = g_dinv[s] * wv * g_dinv[d];
    int p = atomicAdd(&g_cnt[d], 1);
    g_csr[p] = ((ull)__float_as_uint(nr) << 32) | (uint)s;
}

/* ------- fused stage A: 2-wide agg of X + h1 = relu(A@W1+b1) -> fp16 ------ */
__global__ __launch_bounds__(128) void k_aggAH1(const float* __restrict__ X,
                                                const float* __restrict__ W1,
                                                const float* __restrict__ b1) {
    __shared__ __align__(16) uint4 sS[128][9];      /* staged rows, pad */
    __shared__ __align__(16) float sW1[128];
    __shared__ __align__(16) float sb1[64];
    int tid = threadIdx.x;
    if (tid < 128) sW1[tid] = W1[tid];
    if (tid < 64)  sb1[tid] = b1[tid];
    __syncthreads();

    int blk0 = blockIdx.x * 128;
    int idx = blk0 + tid;
    {
        int b = idx & 7;
        int nt = idx >> 3;
        int n = nt % NN;
        int t = nt / NN;
        const float2* base = (const float2*)X + (size_t)(b * TT + T0 + t) * NN;
        float2 x = base[n];
        float sf = g_self[n];
        float ax = sf * x.x, ay = sf * x.y;
        int j = g_off[n], j1 = g_end[n];
        for (; j + 2 <= j1; j += 2) {
            ull e0 = g_csr[j], e1 = g_csr[j + 1];
            int s0 = (int)(e0 & 0xffffffffu);
            int s1 = (int)(e1 & 0xffffffffu);
            float2 xs0 = base[s0];
            float2 xs1 = base[s1];
            float nr0 = __uint_as_float((uint)(e0 >> 32));
            float nr1 = __uint_as_float((uint)(e1 >> 32));
            ax = fmaf(nr0, xs0.x, ax);
            ay = fmaf(nr0, xs0.y, ay);
            ax = fmaf(nr1, xs1.x, ax);
            ay = fmaf(nr1, xs1.y, ay);
        }
        if (j < j1) {
            ull e = g_csr[j];
            int s = (int)(e & 0xffffffffu);
            float nr = __uint_as_float((uint)(e >> 32));
            float2 xs = base[s];
            ax = fmaf(nr, xs.x, ax);
            ay = fmaf(nr, xs.y, ay);
        }
        const float4* w0 = (const float4*)sW1;
        const float4* w1 = (const float4*)(sW1 + 64);
        const float4* bb = (const float4*)sb1;
#pragma unroll
        for (int q8 = 0; q8 < 8; q8++) {
            uint4 o;
            uint* op = (uint*)&o;
#pragma unroll
            for (int h = 0; h < 4; h++) {
                int q = q8 * 2 + (h >> 1);
                float4 W0 = w0[q], W1v = w1[q], Bv = bb[q];
                float v0, v1;
                if ((h & 1) == 0) {
                    v0 = fmaxf(fmaf(ax, W0.x, fmaf(ay, W1v.x, Bv.x)), 0.f);
                    v1 = fmaxf(fmaf(ax, W0.y, fmaf(ay, W1v.y, Bv.y)), 0.f);
                } else {
                    v0 = fmaxf(fmaf(ax, W0.z, fmaf(ay, W1v.z, Bv.z)), 0.f);
                    v1 = fmaxf(fmaf(ax, W0.w, fmaf(ay, W1v.w, Bv.w)), 0.f);
                }
                __half2 hh = __floats2half2_rn(v0, v1);
                op[h] = *(uint*)&hh;
            }
            sS[tid][q8] = o;
        }
    }
    __syncthreads();
    /* coalesced copy-out: block rows contiguous in g_h1h (8 uint4/row) */
    uint4* dst = g_h1h + (size_t)blk0 * 8;
    for (int i = tid; i < 128 * 8; i += 128) {
        int r = i >> 3, c = i & 7;
        dst[i] = sS[r][c];
    }
}

/* ------- fused: 64-wide fp16 gather agg + h2 = relu(C@W2+b2) -> fp16 ------ */
__device__ __forceinline__ void acc_row(const uint4* h1t, int s, int lane,
                                        float nr, float* aA, float* aB) {
    const uint4* rs = h1t + (size_t)s * 64 + lane;
    uint4 v0 = rs[0], v1 = rs[32];
    const __half2* p0 = (const __half2*)&v0;
    const __half2* p1 = (const __half2*)&v1;
#pragma unroll
    for (int k = 0; k < 4; k++) {
        float2 f0 = __half22float2(p0[k]);
        float2 f1 = __half22float2(p1[k]);
        aA[2 * k]     = fmaf(nr, f0.x, aA[2 * k]);
        aA[2 * k + 1] = fmaf(nr, f0.y, aA[2 * k + 1]);
        aB[2 * k]     = fmaf(nr, f1.x, aB[2 * k]);
        aB[2 * k + 1] = fmaf(nr, f1.y, aB[2 * k + 1]);
    }
}

__global__ __launch_bounds__(256) void k_aggCF1(const float* __restrict__ W2,
                                                const float* __restrict__ b2) {
    __shared__ float sC[64 * 65];          /* [r][ci] pad 65; reused for stores */
    __shared__ __align__(16) float sW2[4096];
    int tid = threadIdx.x;
    int t = blockIdx.y;
    for (int i = tid; i < 1024; i += 256)
        ((float4*)sW2)[i] = ((const float4*)W2)[i];

    int warp = tid >> 5, lane = tid & 31;
    int wi = blockIdx.x * 8 + warp;

    const uint4* h1t = g_h1h + (size_t)t * NN * 64;
    const uint4* rn = h1t + (size_t)wi * 64 + lane;
    float sf = g_self[wi];
    float aA[8], aB[8];
    {
        uint4 v0 = rn[0], v1 = rn[32];
        const __half2* p0 = (const __half2*)&v0;
        const __half2* p1 = (const __half2*)&v1;
#pragma unroll
        for (int k = 0; k < 4; k++) {
            float2 f0 = __half22float2(p0[k]);
            float2 f1 = __half22float2(p1[k]);
            aA[2 * k]     = sf * f0.x;
            aA[2 * k + 1] = sf * f0.y;
            aB[2 * k]     = sf * f1.x;
            aB[2 * k + 1] = sf * f1.y;
        }
    }
    int j = g_off[wi], j1 = g_end[wi];
    for (; j + 2 <= j1; j += 2) {
        ull e0 = g_csr[j], e1 = g_csr[j + 1];
        int s0 = (int)(e0 & 0xffffffffu);
        int s1 = (int)(e1 & 0xffffffffu);
        float nr0 = __uint_as_float((uint)(e0 >> 32));
        float nr1 = __uint_as_float((uint)(e1 >> 32));
        const uint4* rs0 = h1t + (size_t)s0 * 64 + lane;
        const uint4* rs1 = h1t + (size_t)s1 * 64 + lane;
        uint4 a0 = rs0[0], a1 = rs0[32];
        uint4 b0 = rs1[0], b1 = rs1[32];
        {
            const __half2* p0 = (const __half2*)&a0;
            const __half2* p1 = (const __half2*)&a1;
            const __half2* q0 = (const __half2*)&b0;
            const __half2* q1 = (const __half2*)&b1;
#pragma unroll
            for (int k = 0; k < 4; k++) {
                float2 f0 = __half22float2(p0[k]);
                float2 f1 = __half22float2(p1[k]);
                float2 g0 = __half22float2(q0[k]);
                float2 g1 = __half22float2(q1[k]);
                aA[2 * k]     = fmaf(nr0, f0.x, aA[2 * k]);
                aA[2 * k + 1] = fmaf(nr0, f0.y, aA[2 * k + 1]);
                aB[2 * k]     = fmaf(nr0, f1.x, aB[2 * k]);
                aB[2 * k + 1] = fmaf(nr0, f1.y, aB[2 * k + 1]);
                aA[2 * k]     = fmaf(nr1, g0.x, aA[2 * k]);
                aA[2 * k + 1] = fmaf(nr1, g0.y, aA[2 * k + 1]);
                aB[2 * k]     = fmaf(nr1, g1.x, aB[2 * k]);
                aB[2 * k + 1] = fmaf(nr1, g1.y, aB[2 * k + 1]);
            }
        }
    }
    if (j < j1) {
        ull e = g_csr[j];
        int s = (int)(e & 0xffffffffu);
        float nr = __uint_as_float((uint)(e >> 32));
        acc_row(h1t, s, lane, nr, aA, aB);
    }
    {
        int bl = lane >> 3;
        int f0 = (lane & 7) * 8;
        float* pA = sC + (warp * 8 + bl) * 65 + f0;
        float* pB = sC + (warp * 8 + 4 + bl) * 65 + f0;
#pragma unroll
        for (int k = 0; k < 8; k++) { pA[k] = aA[k]; pB[k] = aB[k]; }
    }
    __syncthreads();

    int r2 = tid & 31, g = tid >> 5;
    ull accA[4], accB[4];
#pragma unroll
    for (int k = 0; k < 4; k++) {
        float2 bbv = __ldg((const float2*)b2 + g * 4 + k);
        accA[k] = pk2(bbv.x, bbv.y);
        accB[k] = accA[k];
    }
    const float* cA = sC + r2 * 65;
    const float* cB = sC + (r2 + 32) * 65;
#pragma unroll 4
    for (int ci = 0; ci < 64; ci++) {
        ull xA = bc2(cA[ci]);
        ull xB = bc2(cB[ci]);
        const ulonglong2* wp = (const ulonglong2*)(sW2 + ci * 64 + g * 8);
        ulonglong2 wa = wp[0], wb = wp[1];
        accA[0] = fma2(xA, wa.x, accA[0]);
        accA[1] = fma2(xA, wa.y, accA[1]);
        accA[2] = fma2(xA, wb.x, accA[2]);
        accA[3] = fma2(xA, wb.y, accA[3]);
        accB[0] = fma2(xB, wa.x, accB[0]);
        accB[1] = fma2(xB, wa.y, accB[1]);
        accB[2] = fma2(xB, wb.x, accB[2]);
        accB[3] = fma2(xB, wb.y, accB[3]);
    }
    __syncthreads();   /* all GEMM reads of sC done; reuse as half buffer */

    /* stage results as half into sC: [64 rows][pitch 66 halves] */
    __half* sH = (__half*)sC;
#pragma unroll
    for (int k = 0; k < 4; k++) {
        int col = g * 8 + 2 * k;
        float2 u = unp(accA[k]);
        float2 v = unp(accB[k]);
        *(__half2*)(sH + r2 * 66 + col) =
            __floats2half2_rn(fmaxf(u.x, 0.f), fmaxf(u.y, 0.f));
        *(__half2*)(sH + (r2 + 32) * 66 + col) =
            __floats2half2_rn(fmaxf(v.x, 0.f), fmaxf(v.y, 0.f));
    }
    __syncthreads();

    /* coalesced copy-out: 64 rows x 32 uints each */
    size_t nb0 = (size_t)blockIdx.x * 64;
    const uint* sU = (const uint*)sC;
    for (int i = tid; i < 2048; i += 256) {
        int r = i >> 5, cu = i & 31;
        uint v = sU[r * 33 + cu];
        ((uint*)g_h2h)[(nb0 + r) * (KD / 2) + t * 32 + cu] = v;
    }
}

/* ---------------- F2: tensor-core temporal convs + head ------------------- */
#define F2_SMEM (128*P1*2 + 128*P1*2 + 128*P2*2 + 64*P2*2 + (128+64+64)*4)
__global__ __launch_bounds__(256, 1) void k_f2(const float* __restrict__ tc1b,
                                               const float* __restrict__ tc2b,
                                               const float* __restrict__ ow,
                                               const float* __restrict__ ob,
                                               float* __restrict__ out) {
    extern __shared__ __align__(16) char smraw[];
    __half* A_s  = (__half*)smraw;                       /* [128][P1] */
    __half* B1t  = A_s + 128 * P1;                       /* [128][P1] */
    __half* A2   = B1t + 128 * P1;                       /* [128][P2] */
    __half* B2t  = A2 + 128 * P2;                        /* [64][P2]  */
    float*  sb1f = (float*)(B2t + 64 * P2);              /* [128] */
    float*  sb2f = sb1f + 128;                           /* [64] */
    float*  ows  = sb2f + 64;                            /* [64] */

    int tid = threadIdx.x;
    int blk = blockIdx.x;

    {
        const uint4* src = (const uint4*)(g_h2h + (size_t)blk * 128 * KD);
        for (int i = tid; i < 128 * 24; i += 256) {
            int r = i / 24, c = i % 24;
            ((uint4*)(A_s + r * P1))[c] = src[i];
        }
    }
    {
        const uint4* s1 = (const uint4*)g_B1h;
        uint4* d1 = (uint4*)B1t;
        for (int i = tid; i < 128 * P1 / 8; i += 256) d1[i] = s1[i];
        const uint4* s2 = (const uint4*)g_B2h;
        uint4* d2 = (uint4*)B2t;
        for (int i = tid; i < 64 * P2 / 8; i += 256) d2[i] = s2[i];
    }
    if (tid < 128) sb1f[tid] = tc1b[tid & 63];
    else if (tid < 192) sb2f[tid - 128] = tc2b[tid - 128];
    else if (tid < 256) ows[tid - 192] = ow[tid - 192];
    __syncthreads();

    int warp = tid >> 5, lane = tid & 31;
    int g = lane >> 2, tc = lane & 3;
    int m0 = warp * 16;
    int rA = (m0 + g) * P1, rA8 = (m0 + g + 8) * P1;

    float c1[16][4];
#pragma unroll
    for (int nt = 0; nt < 16; nt++) {
        float bb0 = sb1f[nt * 8 + 2 * tc];
        float bb1 = sb1f[nt * 8 + 2 * tc + 1];
        c1[nt][0] = bb0; c1[nt][1] = bb1; c1[nt][2] = bb0; c1[nt][3] = bb1;
    }
#pragma unroll
    for (int k0 = 0; k0 < 12; k0++) {
        int kc = k0 * 16 + 2 * tc;
        uint a0 = *(const uint*)(A_s + rA + kc);
        uint a1 = *(const uint*)(A_s + rA8 + kc);
        uint a2 = *(const uint*)(A_s + rA + kc + 8);
        uint a3 = *(const uint*)(A_s + rA8 + kc + 8);
#pragma unroll
        for (int nt = 0; nt < 16; nt++) {
            const __half* bp = B1t + (nt * 8 + g) * P1 + kc;
            uint b0 = *(const uint*)bp;
            uint b1 = *(const uint*)(bp + 8);
            mma16816(c1[nt][0], c1[nt][1], c1[nt][2], c1[nt][3],
                     a0, a1, a2, a3, b0, b1);
        }
    }
    {
        __half* w0 = A2 + (m0 + g) * P2;
        __half* w8 = A2 + (m0 + g + 8) * P2;
#pragma unroll
        for (int nt = 0; nt < 16; nt++) {
            int col = nt * 8 + 2 * tc;
            *(__half2*)(w0 + col) = __floats2half2_rn(fmaxf(c1[nt][0], 0.f),
                                                      fmaxf(c1[nt][1], 0.f));
            *(__half2*)(w8 + col) = __floats2half2_rn(fmaxf(c1[nt][2], 0.f),
                                                      fmaxf(c1[nt][3], 0.f));
        }
    }
    __syncwarp();

    float c2[8][4];
#pragma unroll
    for (int nt = 0; nt < 8; nt++) {
        float bb0 = sb2f[nt * 8 + 2 * tc];
        float bb1 = sb2f[nt * 8 + 2 * tc + 1];
        c2[nt][0] = bb0; c2[nt][1] = bb1; c2[nt][2] = bb0; c2[nt][3] = bb1;
    }
    int r2A = (m0 + g) * P2, r2A8 = (m0 + g + 8) * P2;
#pragma unroll
    for (int k0 = 0; k0 < 8; k0++) {
        int kc = k0 * 16 + 2 * tc;
        uint a0 = *(const uint*)(A2 + r2A + kc);
        uint a1 = *(const uint*)(A2 + r2A8 + kc);
        uint a2 = *(const uint*)(A2 + r2A + kc + 8);
        uint a3 = *(const uint*)(A2 + r2A8 + kc + 8);
#pragma unroll
        for (int nt = 0; nt < 8; nt++) {
            const __half* bp = B2t + (nt * 8 + g) * P2 + kc;
            uint b0 = *(const uint*)bp;
            uint b1 = *(const uint*)(bp + 8);
            mma16816(c2[nt][0], c2[nt][1], c2[nt][2], c2[nt][3],
                     a0, a1, a2, a3, b0, b1);
        }
    }
    float accR = 0.f, accR8 = 0.f;
#pragma unroll
    for (int nt = 0; nt < 8; nt++) {
        int col = nt * 8 + 2 * tc;
        float w0 = ows[col], w1 = ows[col + 1];
        accR  = fmaf(fmaxf(c2[nt][0], 0.f), w0, accR);
        accR  = fmaf(fmaxf(c2[nt][1], 0.f), w1, accR);
        accR8 = fmaf(fmaxf(c2[nt][2], 0.f), w0, accR8);
        accR8 = fmaf(fmaxf(c2[nt][3], 0.f), w1, accR8);
    }
    accR  += __shfl_xor_sync(0xffffffffu, accR, 1);
    accR  += __shfl_xor_sync(0xffffffffu, accR, 2);
    accR8 += __shfl_xor_sync(0xffffffffu, accR8, 1);
    accR8 += __shfl_xor_sync(0xffffffffu, accR8, 2);
    if (tc == 0) {
        float ob0 = __ldg(ob);
        int nb1 = blk * 128 + m0 + g;
        int nb2 = nb1 + 8;
        out[(nb1 & 7) * NN + (nb1 >> 3)] = accR + ob0;
        out[(nb2 & 7) * NN + (nb2 >> 3)] = accR8 + ob0;
    }
}

/* ---------------- launch ---------------- */
extern "C" void kernel_launch(void* const* d_in, const int* in_sizes, int n_in,
                              void* d_out, int out_size) {
    const float* X    = (const float*)d_in[0];
    const int*   ei   = (const int*)d_in[1];
    const float* ew   = (const float*)d_in[2];
    const float* W1   = (const float*)d_in[3];
    const float* b1   = (const float*)d_in[4];
    const float* W2   = (const float*)d_in[5];
    const float* b2   = (const float*)d_in[6];
    const float* tc1w = (const float*)d_in[7];
    const float* tc1b = (const float*)d_in[8];
    const float* tc2w = (const float*)d_in[9];
    const float* tc2b = (const float*)d_in[10];
    const float* ow   = (const float*)d_in[11];
    const float* ob   = (const float*)d_in[12];
    float* out = (float*)d_out;

    cudaFuncSetAttribute(k_f2, cudaFuncAttributeMaxDynamicSharedMemorySize, F2_SMEM);

    k_prepW<<<32, 256>>>(tc1w, tc2w);        /* includes state zeroing */
    k_deg<<<(EE + 255) / 256, 256>>>(ei, ew);
    k_dinv<<<(NN + 255) / 256, 256>>>();
    k_fill<<<(EE + 255) / 256, 256>>>(ei, ew);
    k_aggAH1<<<ROWS / 128, 128>>>(X, W1, b1);
    dim3 gC(NN / 8, TS);
    k_aggCF1<<<gC, 256>>>(W2, b2);
    k_f2<<<NB / 128, 256, F2_SMEM>>>(tc1b, tc2b, ow, ob, out);
}